// round 14
// baseline (speedup 1.0000x reference)
#include <cuda_runtime.h>

#define BATCH 32
#define NPTS 512
#define DIM 1024
#define KCL 64
#define NROWS (BATCH*NPTS)      /* 16384 */
#define OUTF 1024
#define IN2 (2*DIM*KCL)         /* 131072 */
#define HALF1 (DIM*KCL)         /* 65536 */

// ---------------- scratch (device globals: no allocations allowed) ----------
__device__ float g_act[NROWS*KCL];          // 4 MB
__device__ float g_colsum[KCL];
__device__ float g_colsumsq[KCL];
__device__ float g_asum[BATCH*KCL];
__device__ float g_fv1[BATCH*DIM*KCL];      // 8 MB
__device__ float g_fv2[BATCH*DIM*KCL];      // 8 MB
__device__ float g_colnorm[BATCH*KCL];
__device__ float g_norm2[BATCH];
__device__ float g_scale1[BATCH*KCL];
__device__ float g_scale2[BATCH];
__device__ float g_fvout[BATCH*OUTF];
__device__ float g_gates[BATCH*OUTF];

typedef unsigned long long ull;
typedef unsigned int uint;

// ---------------- f32x2 helpers (FFMA2: 2 FMAs / instr on sm_103a) ----------
__device__ __forceinline__ ull pack2(float lo, float hi){
  ull r;
  asm("mov.b64 %0, {%1, %2};" : "=l"(r)
      : "r"(__float_as_uint(lo)), "r"(__float_as_uint(hi)));
  return r;
}
__device__ __forceinline__ void ffma2(ull &d, ull a, ull b){
  asm("fma.rn.f32x2 %0, %1, %2, %3;" : "=l"(d) : "l"(a), "l"(b), "l"(d));
}
__device__ __forceinline__ float lo32(ull v){ return __uint_as_float((unsigned)(v & 0xffffffffull)); }
__device__ __forceinline__ float hi32(ull v){ return __uint_as_float((unsigned)(v >> 32)); }

// ---------------- bf16 split helpers ----------------------------------------
__device__ __forceinline__ uint prmt_hi(float a, float b){
  uint r;
  asm("prmt.b32 %0, %1, %2, 0x7632;" : "=r"(r)
      : "r"(__float_as_uint(a)), "r"(__float_as_uint(b)));
  return r;
}
__device__ __forceinline__ float trunc_bf(float v){
  return __uint_as_float(__float_as_uint(v) & 0xffff0000u);
}
__device__ __forceinline__ uint cvt_bf2(float upper, float lower){
  uint r;
  asm("cvt.rn.bf16x2.f32 %0, %1, %2;" : "=r"(r) : "f"(upper), "f"(lower));
  return r;
}
__device__ __forceinline__ void mma_bf16(float* c, const uint* a, uint b0, uint b1){
  asm volatile(
    "mma.sync.aligned.m16n8k16.row.col.f32.bf16.bf16.f32 "
    "{%0,%1,%2,%3},{%4,%5,%6,%7},{%8,%9},{%0,%1,%2,%3};"
    : "+f"(c[0]), "+f"(c[1]), "+f"(c[2]), "+f"(c[3])
    : "r"(a[0]), "r"(a[1]), "r"(a[2]), "r"(a[3]), "r"(b0), "r"(b1));
}

// ---------------- K0: zero the atomic accumulators ---------------------------
__global__ void zero_kernel(){
  int i = blockIdx.x*blockDim.x + threadIdx.x;
  if (i < BATCH*OUTF){ g_fvout[i] = 0.f; g_gates[i] = 0.f; }
  if (i < BATCH*KCL){ g_colnorm[i] = 0.f; g_asum[i] = 0.f; }
  if (i < KCL){ g_colsum[i] = 0.f; g_colsumsq[i] = 0.f; }
  if (i < BATCH) g_norm2[i] = 0.f;
}

// ---------------- K1: act_raw = X @ Wc via bf16 TC (+ BN1 stats) ------------
// grid 128 (row tiles of 128), 256 thr = 8 warps; warp w: rows [w*16,w*16+16),
// all 64 n-cols (8 n-tiles). 64 k16 steps, double-buffered, split-bf16 (3 mma).
__global__ __launch_bounds__(256, 2) void act_tc_kernel(
    const float* __restrict__ x, const float* __restrict__ wc){
  __shared__ uint Xh[2][128][12];   // [buf][row][kpair] (8 used)
  __shared__ uint Xl[2][128][12];
  __shared__ uint Wh[2][8][72];     // [buf][kpair][n64]
  __shared__ uint Wl[2][8][72];
  __shared__ float sSum[KCL], sSq[KCL];
  int tid = threadIdx.x, warp = tid >> 5, lane = tid & 31;
  int row0 = blockIdx.x * 128;
  // staging roles
  int rX = tid >> 1;            // X row 0..127
  int qX = (tid & 1) * 2;       // first float4 index (2 per thread)
  int pW = tid >> 5;            // Wc k-pair 0..7
  int nW = (lane) * 2;          // 2 n cols
  if (tid < KCL){ sSum[tid] = 0.f; sSq[tid] = 0.f; }

  float acc[8][4];
  #pragma unroll
  for (int nt=0;nt<8;nt++)
    #pragma unroll
    for (int c=0;c<4;c++) acc[nt][c] = 0.f;

  // prefetch step 0
  float xv[8], wv[4];
  {
    const float* xp = &x[(size_t)(row0+rX)*DIM + qX*4];
    *reinterpret_cast<float4*>(&xv[0]) = *reinterpret_cast<const float4*>(xp);
    *reinterpret_cast<float4*>(&xv[4]) = *reinterpret_cast<const float4*>(xp+4);
    float2 w0 = *reinterpret_cast<const float2*>(&wc[(2*pW  )*KCL + nW]);
    float2 w1 = *reinterpret_cast<const float2*>(&wc[(2*pW+1)*KCL + nW]);
    wv[0]=w0.x; wv[1]=w0.y; wv[2]=w1.x; wv[3]=w1.y;
  }
  // stage buf 0
  {
    #pragma unroll
    for (int q=0;q<2;q++){
      float v0=xv[q*4], v1=xv[q*4+1], v2=xv[q*4+2], v3=xv[q*4+3];
      Xh[0][rX][(qX+q)*2  ] = prmt_hi(v0, v1);
      Xh[0][rX][(qX+q)*2+1] = prmt_hi(v2, v3);
      Xl[0][rX][(qX+q)*2  ] = cvt_bf2(v1-trunc_bf(v1), v0-trunc_bf(v0));
      Xl[0][rX][(qX+q)*2+1] = cvt_bf2(v3-trunc_bf(v3), v2-trunc_bf(v2));
    }
    Wh[0][pW][nW  ] = prmt_hi(wv[0], wv[2]);
    Wh[0][pW][nW+1] = prmt_hi(wv[1], wv[3]);
    Wl[0][pW][nW  ] = cvt_bf2(wv[2]-trunc_bf(wv[2]), wv[0]-trunc_bf(wv[0]));
    Wl[0][pW][nW+1] = cvt_bf2(wv[3]-trunc_bf(wv[3]), wv[1]-trunc_bf(wv[1]));
  }
  __syncthreads();

  int r = lane >> 2, cfr = lane & 3;
  int rb = warp * 16;
  for (int t=0; t<64; t++){
    int cur = t & 1;
    bool more = (t+1) < 64;
    if (more){
      int k0 = (t+1)*16;
      const float* xp = &x[(size_t)(row0+rX)*DIM + k0 + qX*4];
      *reinterpret_cast<float4*>(&xv[0]) = *reinterpret_cast<const float4*>(xp);
      *reinterpret_cast<float4*>(&xv[4]) = *reinterpret_cast<const float4*>(xp+4);
      float2 w0 = *reinterpret_cast<const float2*>(&wc[(k0+2*pW  )*KCL + nW]);
      float2 w1 = *reinterpret_cast<const float2*>(&wc[(k0+2*pW+1)*KCL + nW]);
      wv[0]=w0.x; wv[1]=w0.y; wv[2]=w1.x; wv[3]=w1.y;
    }
    // A fragments (rows rb..rb+15)
    uint ah[4], al[4];
    ah[0]=Xh[cur][rb+r  ][cfr];   ah[1]=Xh[cur][rb+r+8][cfr];
    ah[2]=Xh[cur][rb+r  ][cfr+4]; ah[3]=Xh[cur][rb+r+8][cfr+4];
    al[0]=Xl[cur][rb+r  ][cfr];   al[1]=Xl[cur][rb+r+8][cfr];
    al[2]=Xl[cur][rb+r  ][cfr+4]; al[3]=Xl[cur][rb+r+8][cfr+4];
    #pragma unroll
    for (int nt=0;nt<8;nt++){
      int col = nt*8 + r;
      uint b0h = Wh[cur][cfr][col], b1h = Wh[cur][cfr+4][col];
      uint b0l = Wl[cur][cfr][col], b1l = Wl[cur][cfr+4][col];
      mma_bf16(acc[nt], ah, b0h, b1h);
      mma_bf16(acc[nt], al, b0h, b1h);
      mma_bf16(acc[nt], ah, b0l, b1l);
    }
    if (more){
      int nb = cur ^ 1;
      #pragma unroll
      for (int q=0;q<2;q++){
        float v0=xv[q*4], v1=xv[q*4+1], v2=xv[q*4+2], v3=xv[q*4+3];
        Xh[nb][rX][(qX+q)*2  ] = prmt_hi(v0, v1);
        Xh[nb][rX][(qX+q)*2+1] = prmt_hi(v2, v3);
        Xl[nb][rX][(qX+q)*2  ] = cvt_bf2(v1-trunc_bf(v1), v0-trunc_bf(v0));
        Xl[nb][rX][(qX+q)*2+1] = cvt_bf2(v3-trunc_bf(v3), v2-trunc_bf(v2));
      }
      Wh[nb][pW][nW  ] = prmt_hi(wv[0], wv[2]);
      Wh[nb][pW][nW+1] = prmt_hi(wv[1], wv[3]);
      Wl[nb][pW][nW  ] = cvt_bf2(wv[2]-trunc_bf(wv[2]), wv[0]-trunc_bf(wv[0]));
      Wl[nb][pW][nW+1] = cvt_bf2(wv[3]-trunc_bf(wv[3]), wv[1]-trunc_bf(wv[1]));
    }
    __syncthreads();
  }

  // epilogue: store act + fused BN1 stats (row-sums folded per thread first)
  #pragma unroll
  for (int nt=0;nt<8;nt++){
    #pragma unroll
    for (int j=0;j<2;j++){   // j = c&1 -> n parity
      float va = acc[nt][j];     // row rb+r
      float vb = acc[nt][j+2];   // row rb+r+8
      int n = nt*8 + 2*cfr + j;
      g_act[(size_t)(row0 + rb + r    )*KCL + n] = va;
      g_act[(size_t)(row0 + rb + r + 8)*KCL + n] = vb;
      atomicAdd(&sSum[n], va + vb);
      atomicAdd(&sSq[n],  va*va + vb*vb);
    }
  }
  __syncthreads();
  if (tid < KCL){
    atomicAdd(&g_colsum[tid],   sSum[tid]);
    atomicAdd(&g_colsumsq[tid], sSq[tid]);
  }
}

// ---------------- K2: BN1 + softmax (warp per row) + fused a_sum ------------
__global__ __launch_bounds__(256) void bn_softmax_kernel(
    const float* __restrict__ gamma, const float* __restrict__ beta){
  __shared__ float sbuf[8][KCL];
  int tid = threadIdx.x;
  int w = tid >> 5, lane = tid & 31;
  int row = blockIdx.x*8 + w;
  int b = row >> 9;
  const float inv_n = 1.f / (float)NROWS;
  int k2 = 2*lane;
  float2 cs = *reinterpret_cast<const float2*>(&g_colsum[k2]);
  float2 cq = *reinterpret_cast<const float2*>(&g_colsumsq[k2]);
  float2 ga = *reinterpret_cast<const float2*>(&gamma[k2]);
  float2 be = *reinterpret_cast<const float2*>(&beta[k2]);
  float m0 = cs.x*inv_n, m1 = cs.y*inv_n;
  float sc0 = ga.x*rsqrtf(cq.x*inv_n - m0*m0 + 1e-5f);
  float sc1 = ga.y*rsqrtf(cq.y*inv_n - m1*m1 + 1e-5f);
  float sh0 = be.x - m0*sc0, sh1 = be.y - m1*sc1;

  float2 v = *reinterpret_cast<const float2*>(&g_act[row*KCL + k2]);
  float vn0 = v.x*sc0 + sh0, vn1 = v.y*sc1 + sh1;
  float mx = fmaxf(vn0, vn1);
  #pragma unroll
  for (int o=16;o>0;o>>=1) mx = fmaxf(mx, __shfl_xor_sync(0xffffffffu, mx, o));
  float e0 = __expf(vn0 - mx), e1 = __expf(vn1 - mx);
  float s = e0 + e1;
  #pragma unroll
  for (int o=16;o>0;o>>=1) s += __shfl_xor_sync(0xffffffffu, s, o);
  float inv = 1.f / s;
  float p0 = e0*inv, p1 = e1*inv;
  *reinterpret_cast<float2*>(&g_act[row*KCL + k2]) = make_float2(p0, p1);
  *reinterpret_cast<float2*>(&sbuf[w][k2]) = make_float2(p0, p1);
  __syncthreads();
  if (tid < KCL){
    float t = 0.f;
    #pragma unroll
    for (int i=0;i<8;i++) t += sbuf[i][tid];
    atomicAdd(&g_asum[b*KCL + tid], t);
  }
}

// ---------------- K4: einsum via bf16 tensor cores + fused transform --------
__global__ __launch_bounds__(256, 2) void einsum_tc_kernel(
    const float* __restrict__ x,
    const float* __restrict__ covw, const float* __restrict__ cw2w){
  __shared__ uint aTh[2][64][12];
  __shared__ uint aTl[2][64][12];
  __shared__ uint xh[2][8][72];
  __shared__ uint xl[2][8][72];
  __shared__ uint qh[2][8][72];
  __shared__ uint ql[2][8][72];
  __shared__ float sAsum[KCL];
  __shared__ float sCol[KCL];
  __shared__ float swp[8];
  int tid = threadIdx.x, warp = tid >> 5, lane = tid & 31;
  int b = blockIdx.y, d0 = blockIdx.x * 64;
  int wm = warp & 1, wn = warp >> 1;
  int px  = tid >> 5;
  int dcx = (tid & 31) * 2;
  int ka  = tid & 63;
  int pa  = (tid >> 6) * 2;
  if (tid < KCL){ sAsum[tid] = g_asum[b*KCL + tid]; sCol[tid] = 0.f; }

  float acc1[2][2][4], acc2[2][2][4];
  #pragma unroll
  for (int mt=0;mt<2;mt++)
    #pragma unroll
    for (int nt=0;nt<2;nt++)
      #pragma unroll
      for (int c=0;c<4;c++){ acc1[mt][nt][c]=0.f; acc2[mt][nt][c]=0.f; }

  const float* xrow = x + (size_t)b*NPTS*DIM + d0;
  const float* arow = g_act + (size_t)b*NPTS*KCL;

  float xv[4], av[4];
  {
    float2 t0 = *reinterpret_cast<const float2*>(&xrow[(2*px  )*DIM + dcx]);
    float2 t1 = *reinterpret_cast<const float2*>(&xrow[(2*px+1)*DIM + dcx]);
    xv[0]=t0.x; xv[1]=t0.y; xv[2]=t1.x; xv[3]=t1.y;
    #pragma unroll
    for (int j=0;j<4;j++) av[j] = arow[(2*pa+j)*KCL + ka];
  }
  {
    float q0=xv[0]*xv[0], q1=xv[1]*xv[1], q2=xv[2]*xv[2], q3=xv[3]*xv[3];
    xh[0][px][dcx  ] = prmt_hi(xv[0], xv[2]);
    xh[0][px][dcx+1] = prmt_hi(xv[1], xv[3]);
    xl[0][px][dcx  ] = cvt_bf2(xv[2]-trunc_bf(xv[2]), xv[0]-trunc_bf(xv[0]));
    xl[0][px][dcx+1] = cvt_bf2(xv[3]-trunc_bf(xv[3]), xv[1]-trunc_bf(xv[1]));
    qh[0][px][dcx  ] = prmt_hi(q0, q2);
    qh[0][px][dcx+1] = prmt_hi(q1, q3);
    ql[0][px][dcx  ] = cvt_bf2(q2-trunc_bf(q2), q0-trunc_bf(q0));
    ql[0][px][dcx+1] = cvt_bf2(q3-trunc_bf(q3), q1-trunc_bf(q1));
    aTh[0][ka][pa  ] = prmt_hi(av[0], av[1]);
    aTh[0][ka][pa+1] = prmt_hi(av[2], av[3]);
    aTl[0][ka][pa  ] = cvt_bf2(av[1]-trunc_bf(av[1]), av[0]-trunc_bf(av[0]));
    aTl[0][ka][pa+1] = cvt_bf2(av[3]-trunc_bf(av[3]), av[2]-trunc_bf(av[2]));
  }
  __syncthreads();

  int r = lane >> 2, cfr = lane & 3;
  for (int t=0; t<32; t++){
    int cur = t & 1;
    bool more = (t+1) < 32;
    if (more){
      int n0 = (t+1)*16;
      float2 t0 = *reinterpret_cast<const float2*>(&xrow[(n0+2*px  )*DIM + dcx]);
      float2 t1 = *reinterpret_cast<const float2*>(&xrow[(n0+2*px+1)*DIM + dcx]);
      xv[0]=t0.x; xv[1]=t0.y; xv[2]=t1.x; xv[3]=t1.y;
      #pragma unroll
      for (int j=0;j<4;j++) av[j] = arow[(n0+2*pa+j)*KCL + ka];
    }
    uint ah[2][4], al[2][4];
    #pragma unroll
    for (int mt=0;mt<2;mt++){
      int rb = wm*32 + mt*16;
      ah[mt][0]=aTh[cur][rb+r  ][cfr];   ah[mt][1]=aTh[cur][rb+r+8][cfr];
      ah[mt][2]=aTh[cur][rb+r  ][cfr+4]; ah[mt][3]=aTh[cur][rb+r+8][cfr+4];
      al[mt][0]=aTl[cur][rb+r  ][cfr];   al[mt][1]=aTl[cur][rb+r+8][cfr];
      al[mt][2]=aTl[cur][rb+r  ][cfr+4]; al[mt][3]=aTl[cur][rb+r+8][cfr+4];
    }
    #pragma unroll
    for (int nt=0;nt<2;nt++){
      int col = wn*16 + nt*8 + r;
      uint bxh0 = xh[cur][cfr][col], bxh1 = xh[cur][cfr+4][col];
      uint bxl0 = xl[cur][cfr][col], bxl1 = xl[cur][cfr+4][col];
      uint bqh0 = qh[cur][cfr][col], bqh1 = qh[cur][cfr+4][col];
      uint bql0 = ql[cur][cfr][col], bql1 = ql[cur][cfr+4][col];
      #pragma unroll
      for (int mt=0;mt<2;mt++){
        mma_bf16(acc1[mt][nt], ah[mt], bxh0, bxh1);
        mma_bf16(acc1[mt][nt], al[mt], bxh0, bxh1);
        mma_bf16(acc1[mt][nt], ah[mt], bxl0, bxl1);
        mma_bf16(acc2[mt][nt], ah[mt], bqh0, bqh1);
        mma_bf16(acc2[mt][nt], al[mt], bqh0, bqh1);
        mma_bf16(acc2[mt][nt], ah[mt], bql0, bql1);
      }
    }
    if (more){
      int nxt = cur ^ 1;
      float q0=xv[0]*xv[0], q1=xv[1]*xv[1], q2=xv[2]*xv[2], q3=xv[3]*xv[3];
      xh[nxt][px][dcx  ] = prmt_hi(xv[0], xv[2]);
      xh[nxt][px][dcx+1] = prmt_hi(xv[1], xv[3]);
      xl[nxt][px][dcx  ] = cvt_bf2(xv[2]-trunc_bf(xv[2]), xv[0]-trunc_bf(xv[0]));
      xl[nxt][px][dcx+1] = cvt_bf2(xv[3]-trunc_bf(xv[3]), xv[1]-trunc_bf(xv[1]));
      qh[nxt][px][dcx  ] = prmt_hi(q0, q2);
      qh[nxt][px][dcx+1] = prmt_hi(q1, q3);
      ql[nxt][px][dcx  ] = cvt_bf2(q2-trunc_bf(q2), q0-trunc_bf(q0));
      ql[nxt][px][dcx+1] = cvt_bf2(q3-trunc_bf(q3), q1-trunc_bf(q1));
      aTh[nxt][ka][pa  ] = prmt_hi(av[0], av[1]);
      aTh[nxt][ka][pa+1] = prmt_hi(av[2], av[3]);
      aTl[nxt][ka][pa  ] = cvt_bf2(av[1]-trunc_bf(av[1]), av[0]-trunc_bf(av[0]));
      aTl[nxt][ka][pa+1] = cvt_bf2(av[3]-trunc_bf(av[3]), av[2]-trunc_bf(av[2]));
    }
    __syncthreads();
  }

  float pn2 = 0.f;
  float pcol[2][2] = {{0.f,0.f},{0.f,0.f}};
  #pragma unroll
  for (int mt=0;mt<2;mt++){
    #pragma unroll
    for (int nt=0;nt<2;nt++){
      #pragma unroll
      for (int c=0;c<4;c++){
        int k   = wm*32 + mt*16 + r + ((c>=2)?8:0);
        int dl  = wn*16 + nt*8 + 2*cfr + (c&1);
        int dgl = d0 + dl;
        int widx = dgl*KCL + k;
        float cwm = cw2w[widx];
        float cvm = covw[widx];
        float asum = sAsum[k];
        float cwv = cvm*cvm + 1e-6f;
        float rc = __fdividef(1.f, cwv);
        float f1r = acc1[mt][nt][c], f2r = acc2[mt][nt][c];
        float f1t = (f1r - asum*cwm) * rc;
        float f2t = (asum*cwm*cwm + f2r - 2.f*f1r*cwm) * rc * rc - asum;
        g_fv1[(b*DIM + dgl)*KCL + k] = f1t;
        g_fv2[(b*DIM + dgl)*KCL + k] = f2t;
        pcol[mt][c>>1 & 1] += f1t*f1t;
        pn2 += f2t*f2t;
      }
    }
  }
  #pragma unroll
  for (int mt=0;mt<2;mt++)
    #pragma unroll
    for (int h=0;h<2;h++){
      int k = wm*32 + mt*16 + r + h*8;
      atomicAdd(&sCol[k], pcol[mt][h]);
    }
  #pragma unroll
  for (int o=16;o>0;o>>=1) pn2 += __shfl_xor_sync(0xffffffffu, pn2, o);
  if (lane==0) swp[warp] = pn2;
  __syncthreads();
  if (tid < KCL) atomicAdd(&g_colnorm[b*KCL + tid], sCol[tid]);
  if (tid == 0){
    float t = 0.f;
    #pragma unroll
    for (int i=0;i<8;i++) t += swp[i];
    atomicAdd(&g_norm2[b], t);
  }
}

// ---------------- K5b: tiny — fold the two-stage norms into scale tables ----
__global__ __launch_bounds__(64) void scale_kernel(){
  int b = blockIdx.x, k = threadIdx.x;
  float cn = g_colnorm[b*KCL + k];
  float inv1 = 1.f / fmaxf(sqrtf(cn), 1e-12f);
  float contrib = cn * inv1 * inv1;
  float t = contrib;
  #pragma unroll
  for (int o=16;o>0;o>>=1) t += __shfl_xor_sync(0xffffffffu, t, o);
  __shared__ float sw[2];
  if ((k&31)==0) sw[k>>5] = t;
  __syncthreads();
  float n1 = sqrtf(sw[0] + sw[1]);
  g_scale1[b*KCL + k] = inv1 / fmaxf(n1, 1e-12f);
  if (k == 0) g_scale2[b] = 1.f / fmaxf(sqrtf(g_norm2[b]), 1e-12f);
}

// ---------------- K6: hidden1 bf16-TC with cp.async 4-stage W pipeline ------
#define FC1_WPAD 260
#define FC1_SMEM (4*16*FC1_WPAD*4 + 2*32*68*4*2)
__global__ __launch_bounds__(256, 2) void gemm_fc1_hmma(
    const float* __restrict__ W){
  extern __shared__ char smemraw[];
  float (*WsS)[16][FC1_WPAD] = reinterpret_cast<float(*)[16][FC1_WPAD]>(smemraw);
  uint (*AhS)[32][68] = reinterpret_cast<uint(*)[32][68]>(smemraw + 4*16*FC1_WPAD*4);
  uint (*AlS)[32][68] = reinterpret_cast<uint(*)[32][68]>(smemraw + 4*16*FC1_WPAD*4 + 2*32*68*4);

  int tid = threadIdx.x;
  int warp = tid >> 5, lane = tid & 31;
  int i0 = blockIdx.y * 2048;
  int o0 = blockIdx.x * 256;

  const float* A;
  int iA0, half1;
  if (i0 < HALF1){ A = g_fv1; iA0 = i0; half1 = 1; }
  else { A = g_fv2; iA0 = i0 - HALF1; half1 = 0; }

  int rA = tid >> 3;
  int pA = (tid & 7) * 8;
  float sreg[16];
  if (half1){
    #pragma unroll
    for (int j=0;j<16;j++) sreg[j] = g_scale1[rA*KCL + ((pA*2 + j) & 63)];
  } else {
    float s = g_scale2[rA];
    #pragma unroll
    for (int j=0;j<16;j++) sreg[j] = s;
  }

  int wrow0 = tid >> 6;
  int wcol0 = (tid & 63) * 4;

  int wcol = warp*32 + (lane >> 2);
  int krow = 2*(lane & 3);
  int r = lane >> 2, cfr = lane & 3;

  float acc[2][4][4];
  #pragma unroll
  for (int mt=0;mt<2;mt++)
    #pragma unroll
    for (int nt=0;nt<4;nt++)
      #pragma unroll
      for (int c=0;c<4;c++) acc[mt][nt][c] = 0.f;

  #pragma unroll
  for (int s=0; s<3; s++){
    const float* base = W + (size_t)(i0 + s*16)*OUTF + o0;
    #pragma unroll
    for (int p=0;p<4;p++){
      int row = wrow0 + p*4;
      uint dst = (uint)__cvta_generic_to_shared(&WsS[s][row][wcol0]);
      const float* src = base + row*OUTF + wcol0;
      asm volatile("cp.async.cg.shared.global [%0], [%1], 16;" :: "r"(dst), "l"(src));
    }
    asm volatile("cp.async.commit_group;");
  }

  {
    const float* ap = &A[rA*HALF1 + iA0 + pA*2];
    float v[16];
    #pragma unroll
    for (int p=0;p<4;p++){
      float4 t4 = *reinterpret_cast<const float4*>(ap + p*4);
      v[p*4+0]=t4.x; v[p*4+1]=t4.y; v[p*4+2]=t4.z; v[p*4+3]=t4.w;
    }
    #pragma unroll
    for (int j=0;j<8;j++){
      float v0 = v[2*j]*sreg[2*j], v1 = v[2*j+1]*sreg[2*j+1];
      AhS[0][rA][pA+j] = prmt_hi(v0, v1);
      AlS[0][rA][pA+j] = cvt_bf2(v1 - trunc_bf(v1), v0 - trunc_bf(v0));
    }
  }
  asm volatile("cp.async.wait_group 2;");
  __syncthreads();

  float vnext[16];
  for (int t=0; t<128; t++){
    int st = t & 3;
    int ss = t >> 3, sin = t & 7, buf = ss & 1;
    if (t+3 < 128){
      const float* base = W + (size_t)(i0 + (t+3)*16)*OUTF + o0;
      int s = (t+3) & 3;
      #pragma unroll
      for (int p=0;p<4;p++){
        int row = wrow0 + p*4;
        uint dst = (uint)__cvta_generic_to_shared(&WsS[s][row][wcol0]);
        const float* src = base + row*OUTF + wcol0;
        asm volatile("cp.async.cg.shared.global [%0], [%1], 16;" :: "r"(dst), "l"(src));
      }
      asm volatile("cp.async.commit_group;");
    }
    if (sin == 0 && ss+1 < 16){
      const float* ap = &A[rA*HALF1 + iA0 + (ss+1)*128 + pA*2];
      #pragma unroll
      for (int p=0;p<4;p++){
        float4 t4 = *reinterpret_cast<const float4*>(ap + p*4);
        vnext[p*4+0]=t4.x; vnext[p*4+1]=t4.y; vnext[p*4+2]=t4.z; vnext[p*4+3]=t4.w;
      }
    }
    float wcur[16];
    #pragma unroll
    for (int nt=0;nt<4;nt++){
      wcur[nt*4+0] = WsS[st][krow  ][wcol + nt*8];
      wcur[nt*4+1] = WsS[st][krow+1][wcol + nt*8];
      wcur[nt*4+2] = WsS[st][krow+8][wcol + nt*8];
      wcur[nt*4+3] = WsS[st][krow+9][wcol + nt*8];
    }
    uint ah[8], al[8];
    #pragma unroll
    for (int mt=0;mt<2;mt++){
      int rr = r + mt*16;
      ah[mt*4+0] = AhS[buf][rr  ][sin*8+cfr];
      ah[mt*4+1] = AhS[buf][rr+8][sin*8+cfr];
      ah[mt*4+2] = AhS[buf][rr  ][sin*8+cfr+4];
      ah[mt*4+3] = AhS[buf][rr+8][sin*8+cfr+4];
      al[mt*4+0] = AlS[buf][rr  ][sin*8+cfr];
      al[mt*4+1] = AlS[buf][rr+8][sin*8+cfr];
      al[mt*4+2] = AlS[buf][rr  ][sin*8+cfr+4];
      al[mt*4+3] = AlS[buf][rr+8][sin*8+cfr+4];
    }
    uint whi[8], wlo[8];
    #pragma unroll
    for (int nt=0;nt<4;nt++){
      float w0 = wcur[nt*4+0], w1 = wcur[nt*4+1];
      float w2 = wcur[nt*4+2], w3 = wcur[nt*4+3];
      whi[nt*2+0] = prmt_hi(w0, w1);
      whi[nt*2+1] = prmt_hi(w2, w3);
      wlo[nt*2+0] = cvt_bf2(w1 - trunc_bf(w1), w0 - trunc_bf(w0));
      wlo[nt*2+1] = cvt_bf2(w3 - trunc_bf(w3), w2 - trunc_bf(w2));
    }
    #pragma unroll
    for (int mt=0;mt<2;mt++){
      #pragma unroll
      for (int nt=0;nt<4;nt++){
        mma_bf16(acc[mt][nt], &ah[mt*4], whi[nt*2], whi[nt*2+1]);
        mma_bf16(acc[mt][nt], &al[mt*4], whi[nt*2], whi[nt*2+1]);
        mma_bf16(acc[mt][nt], &ah[mt*4], wlo[nt*2], wlo[nt*2+1]);
      }
    }
    if (sin == 7 && ss+1 < 16){
      int nb = buf ^ 1;
      #pragma unroll
      for (int j=0;j<8;j++){
        float v0 = vnext[2*j]*sreg[2*j], v1 = vnext[2*j+1]*sreg[2*j+1];
        AhS[nb][rA][pA+j] = prmt_hi(v0, v1);
        AlS[nb][rA][pA+j] = cvt_bf2(v1 - trunc_bf(v1), v0 - trunc_bf(v0));
      }
    }
    if (t+1 < 128){
      if (t+3 < 128){ asm volatile("cp.async.wait_group 2;"); }
      else          { asm volatile("cp.async.wait_group 0;"); }
      __syncthreads();
    }
  }

  #pragma unroll
  for (int mt=0;mt<2;mt++)
    #pragma unroll
    for (int nt=0;nt<4;nt++)
      #pragma unroll
      for (int c=0;c<4;c++){
        int row = (lane>>2) + ((c>=2)?8:0) + mt*16;
        int col = o0 + warp*32 + nt*8 + 2*(lane&3) + (c&1);
        atomicAdd(&g_fvout[row*OUTF + col], acc[mt][nt][c]);
      }
}

// ---------------- K7a: gating GEMM (fp32 FFMA2, small) ----------------------
#define FC_KT 16
__global__ __launch_bounds__(256) void gemm_fc_kernel(
    const float* __restrict__ W, int ichunk){
  __shared__ float Ws[2][FC_KT][256];
  __shared__ float fs[2][FC_KT][32];
  int tid = threadIdx.x;
  int o0 = blockIdx.x * 256;
  int i0 = blockIdx.y * ichunk;
  int og = tid & 63, bg = tid >> 6;
  const float* A = g_fvout; float* out = g_gates;
  int bload = tid & 31;
  int rload0 = (tid >> 5)*2;

  int T = ichunk / FC_KT;
  int roff[4], coff[4];
  #pragma unroll
  for (int p=0;p<4;p++){
    int off = p*1024 + tid*4;
    roff[p] = off >> 8; coff[p] = off & 255;
  }

  ull acc[8][2];
  #pragma unroll
  for (int bb=0;bb<8;bb++){ acc[bb][0]=0ull; acc[bb][1]=0ull; }

  float4 pw[4]; float pa0, pa1;
  {
    #pragma unroll
    for (int p=0;p<4;p++)
      pw[p] = *reinterpret_cast<const float4*>(&W[(i0+roff[p])*OUTF + o0 + coff[p]]);
    pa0 = A[bload*OUTF + i0 + rload0];
    pa1 = A[bload*OUTF + i0 + rload0 + 1];
  }
  #pragma unroll
  for (int p=0;p<4;p++)
    *reinterpret_cast<float4*>(&Ws[0][roff[p]][coff[p]]) = pw[p];
  fs[0][rload0][bload] = pa0;
  fs[0][rload0+1][bload] = pa1;
  __syncthreads();

  for (int t=0; t<T; t++){
    int cur = t & 1;
    bool more = (t+1) < T;
    if (more){
      int i  = i0 + (t+1)*FC_KT;
      #pragma unroll
      for (int p=0;p<4;p++)
        pw[p] = *reinterpret_cast<const float4*>(&W[(i+roff[p])*OUTF + o0 + coff[p]]);
      pa0 = A[bload*OUTF + i + rload0];
      pa1 = A[bload*OUTF + i + rload0 + 1];
    }
    #pragma unroll
    for (int ii=0; ii<FC_KT; ii++){
      const ull* wp = reinterpret_cast<const ull*>(&Ws[cur][ii][og*4]);
      ull w0 = wp[0], w1 = wp[1];
      float4 fa = *reinterpret_cast<const float4*>(&fs[cur][ii][bg*8]);
      float4 fb = *reinterpret_cast<const float4*>(&fs[cur][ii][bg*8+4]);
      ull a0 = pack2(fa.x,fa.x), a1 = pack2(fa.y,fa.y);
      ull a2 = pack2(fa.z,fa.z), a3 = pack2(fa.w,fa.w);
      ull a4 = pack2(fb.x,fb.x), a5 = pack2(fb.y,fb.y);
      ull a6 = pack2(fb.z,fb.z), a7 = pack2(fb.w,fb.w);
      ffma2(acc[0][0], a0, w0); ffma2(acc[0][1], a0, w1);
      ffma2(acc[1][0], a1, w0); ffma2(acc[1][1], a1, w1);
      ffma2(acc[2][0], a2, w0); ffma2(acc[2][1], a2, w1);
      ffma2(acc[3][0], a3, w0); ffma2(acc[3][1], a3, w1);
      ffma2(acc[4][0], a4, w0); ffma2(acc[4][1], a4, w1);
      ffma2(acc[5][0], a5, w0); ffma2(acc[5][1], a5, w1);
      ffma2(acc[6][0], a6, w0); ffma2(acc[6][1], a6, w1);
      ffma2(acc[7][0], a7, w0); ffma2(acc[7][1], a7, w1);
    }
    if (more){
      int nxt = (t+1) & 1;
      #pragma unroll
      for (int p=0;p<4;p++)
        *reinterpret_cast<float4*>(&Ws[nxt][roff[p]][coff[p]]) = pw[p];
      fs[nxt][rload0][bload] = pa0;
      fs[nxt][rload0+1][bload] = pa1;
    }
    __syncthreads();
  }

  #pragma unroll
  for (int bb=0;bb<8;bb++){
    int b = bg*8 + bb;
    #pragma unroll
    for (int t=0;t<2;t++){
      int base = b*OUTF + o0 + og*4 + t*2;
      atomicAdd(&out[base],   lo32(acc[bb][t]));
      atomicAdd(&out[base+1], hi32(acc[bb][t]));
    }
  }
}

// ---------------- K7b: BN2 (batch stats over 32) + sigmoid gate -------------
__global__ __launch_bounds__(256) void bn2_gate_kernel(
    const float* __restrict__ g2, const float* __restrict__ b2,
    float* __restrict__ out){
  int o = blockIdx.x*blockDim.x + threadIdx.x;   // 0..1023
  float m=0.f, s=0.f;
  #pragma unroll 8
  for (int b=0;b<BATCH;b++){ float v = g_gates[b*OUTF + o]; m += v; s += v*v; }
  m *= (1.f/BATCH);
  float var = s*(1.f/BATCH) - m*m;
  float rs = rsqrtf(var + 1e-5f);
  float ga = g2[o], be = b2[o];
  #pragma unroll 8
  for (int b=0;b<BATCH;b++){
    float v = (g_gates[b*OUTF + o] - m)*rs*ga + be;
    float sig = 1.f/(1.f + expf(-v));
    out[b*OUTF + o] = g_fvout[b*OUTF + o] * sig;
  }
}

// ---------------------------------------------------------------------------
extern "C" void kernel_launch(void* const* d_in, const int* in_sizes, int n_in,
                              void* d_out, int out_size){
  const float* x   = (const float*)d_in[0];   // [32,512,1024]
  const float* wc  = (const float*)d_in[1];   // [1024,64]
  const float* cov = (const float*)d_in[2];   // [1024,64]
  const float* cw2 = (const float*)d_in[3];   // [1,1024,64]
  const float* w1  = (const float*)d_in[4];   // [131072,1024]
  const float* g1  = (const float*)d_in[5];   // [64]
  const float* b1  = (const float*)d_in[6];   // [64]
  const float* wg  = (const float*)d_in[7];   // [1024,1024]
  const float* g2  = (const float*)d_in[8];   // [1024]
  const float* b2  = (const float*)d_in[9];   // [1024]
  float* out = (float*)d_out;                 // [32,1024]

  cudaFuncSetAttribute(gemm_fc1_hmma,
      cudaFuncAttributeMaxDynamicSharedMemorySize, FC1_SMEM);

  zero_kernel<<<128, 256>>>();
  act_tc_kernel<<<128, 256>>>(x, wc);
  bn_softmax_kernel<<<2048, 256>>>(g1, b1);
  einsum_tc_kernel<<<dim3(16, 32), 256>>>(x, cov, cw2);
  scale_kernel<<<BATCH, 64>>>();
  gemm_fc1_hmma<<<dim3(4, 64), 256, FC1_SMEM>>>(w1); // hidden1 (TC + cp.async)
  gemm_fc_kernel<<<dim3(4, 16), 256>>>(wg, 64);      // gating (fp32)
  bn2_gate_kernel<<<4, 256>>>(g2, b2, out);
}

// round 15
// speedup vs baseline: 1.4767x; 1.4767x over previous
#include <cuda_runtime.h>

#define BATCH 32
#define NPTS 512
#define DIM 1024
#define KCL 64
#define NROWS (BATCH*NPTS)      /* 16384 */
#define OUTF 1024
#define IN2 (2*DIM*KCL)         /* 131072 */
#define HALF1 (DIM*KCL)         /* 65536 */

// ---------------- scratch (device globals: no allocations allowed) ----------
__device__ float g_act[NROWS*KCL];          // 4 MB
__device__ float g_colsum[KCL];
__device__ float g_colsumsq[KCL];
__device__ float g_asum[BATCH*KCL];
__device__ float g_fv1[BATCH*DIM*KCL];      // 8 MB
__device__ float g_fv2[BATCH*DIM*KCL];      // 8 MB
__device__ float g_colnorm[BATCH*KCL];
__device__ float g_norm2[BATCH];
__device__ float g_scale1[BATCH*KCL];
__device__ float g_scale2[BATCH];
__device__ float g_fvout[BATCH*OUTF];
__device__ float g_gates[BATCH*OUTF];

typedef unsigned long long ull;
typedef unsigned int uint;

// ---------------- f32x2 helpers (FFMA2: 2 FMAs / instr on sm_103a) ----------
__device__ __forceinline__ ull pack2(float lo, float hi){
  ull r;
  asm("mov.b64 %0, {%1, %2};" : "=l"(r)
      : "r"(__float_as_uint(lo)), "r"(__float_as_uint(hi)));
  return r;
}
__device__ __forceinline__ void ffma2(ull &d, ull a, ull b){
  asm("fma.rn.f32x2 %0, %1, %2, %3;" : "=l"(d) : "l"(a), "l"(b), "l"(d));
}
__device__ __forceinline__ float lo32(ull v){ return __uint_as_float((unsigned)(v & 0xffffffffull)); }
__device__ __forceinline__ float hi32(ull v){ return __uint_as_float((unsigned)(v >> 32)); }

// ---------------- bf16 split helpers ----------------------------------------
__device__ __forceinline__ uint prmt_hi(float a, float b){
  uint r;
  asm("prmt.b32 %0, %1, %2, 0x7632;" : "=r"(r)
      : "r"(__float_as_uint(a)), "r"(__float_as_uint(b)));
  return r;
}
__device__ __forceinline__ float trunc_bf(float v){
  return __uint_as_float(__float_as_uint(v) & 0xffff0000u);
}
__device__ __forceinline__ uint cvt_bf2(float upper, float lower){
  uint r;
  asm("cvt.rn.bf16x2.f32 %0, %1, %2;" : "=r"(r) : "f"(upper), "f"(lower));
  return r;
}
__device__ __forceinline__ void mma_bf16(float* c, const uint* a, uint b0, uint b1){
  asm volatile(
    "mma.sync.aligned.m16n8k16.row.col.f32.bf16.bf16.f32 "
    "{%0,%1,%2,%3},{%4,%5,%6,%7},{%8,%9},{%0,%1,%2,%3};"
    : "+f"(c[0]), "+f"(c[1]), "+f"(c[2]), "+f"(c[3])
    : "r"(a[0]), "r"(a[1]), "r"(a[2]), "r"(a[3]), "r"(b0), "r"(b1));
}

// ---------------- K0: zero the atomic accumulators ---------------------------
__global__ void zero_kernel(){
  int i = blockIdx.x*blockDim.x + threadIdx.x;
  if (i < BATCH*OUTF){ g_fvout[i] = 0.f; g_gates[i] = 0.f; }
  if (i < BATCH*KCL){ g_colnorm[i] = 0.f; g_asum[i] = 0.f; }
  if (i < KCL){ g_colsum[i] = 0.f; g_colsumsq[i] = 0.f; }
  if (i < BATCH) g_norm2[i] = 0.f;
}

// ---------------- K1: act_raw = X @ Wc  (+ column sum / sumsq for BN1) ------
// BK=64: halved barrier count vs BK=32 variant.
__global__ __launch_bounds__(256) void gemm_act_kernel(
    const float* __restrict__ x, const float* __restrict__ wc){
  __shared__ float As[64][65];
  __shared__ float Bs[64][64];
  __shared__ float sSum[KCL], sSq[KCL];
  int tid = threadIdx.x;
  int row0 = blockIdx.x * 64;
  int tx = tid & 15, ty = tid >> 4;
  ull acc[4][2];
  #pragma unroll
  for (int i=0;i<4;i++){ acc[i][0]=0ull; acc[i][1]=0ull; }
  if (tid < KCL){ sSum[tid]=0.f; sSq[tid]=0.f; }

  for (int d0=0; d0<DIM; d0+=64){
    #pragma unroll
    for (int l=tid; l<4096; l+=256){
      int r=l>>6, c=l&63;
      As[r][c] = x[(row0+r)*DIM + d0 + c];
      Bs[r][c] = wc[(d0+r)*KCL + c];
    }
    __syncthreads();
    #pragma unroll
    for (int dd=0; dd<64; dd++){
      const ull* bp = reinterpret_cast<const ull*>(&Bs[dd][tx*4]);
      ull b0 = bp[0], b1 = bp[1];
      #pragma unroll
      for (int i=0;i<4;i++){
        float a = As[ty*4+i][dd];
        ull ap = pack2(a, a);
        ffma2(acc[i][0], ap, b0);
        ffma2(acc[i][1], ap, b1);
      }
    }
    __syncthreads();
  }
  float ps[4]={0,0,0,0}, pq[4]={0,0,0,0};
  #pragma unroll
  for (int i=0;i<4;i++){
    float v0=lo32(acc[i][0]), v1=hi32(acc[i][0]);
    float v2=lo32(acc[i][1]), v3=hi32(acc[i][1]);
    *reinterpret_cast<float4*>(&g_act[(row0+ty*4+i)*KCL + tx*4]) =
        make_float4(v0,v1,v2,v3);
    ps[0]+=v0; ps[1]+=v1; ps[2]+=v2; ps[3]+=v3;
    pq[0]+=v0*v0; pq[1]+=v1*v1; pq[2]+=v2*v2; pq[3]+=v3*v3;
  }
  #pragma unroll
  for (int j=0;j<4;j++){
    atomicAdd(&sSum[tx*4+j], ps[j]);
    atomicAdd(&sSq [tx*4+j], pq[j]);
  }
  __syncthreads();
  if (tid < KCL){
    atomicAdd(&g_colsum[tid],   sSum[tid]);
    atomicAdd(&g_colsumsq[tid], sSq[tid]);
  }
}

// ---------------- K2: BN1 + softmax (warp per row) + fused a_sum ------------
__global__ __launch_bounds__(256) void bn_softmax_kernel(
    const float* __restrict__ gamma, const float* __restrict__ beta){
  __shared__ float sbuf[8][KCL];
  int tid = threadIdx.x;
  int w = tid >> 5, lane = tid & 31;
  int row = blockIdx.x*8 + w;
  int b = row >> 9;
  const float inv_n = 1.f / (float)NROWS;
  int k2 = 2*lane;
  float2 cs = *reinterpret_cast<const float2*>(&g_colsum[k2]);
  float2 cq = *reinterpret_cast<const float2*>(&g_colsumsq[k2]);
  float2 ga = *reinterpret_cast<const float2*>(&gamma[k2]);
  float2 be = *reinterpret_cast<const float2*>(&beta[k2]);
  float m0 = cs.x*inv_n, m1 = cs.y*inv_n;
  float sc0 = ga.x*rsqrtf(cq.x*inv_n - m0*m0 + 1e-5f);
  float sc1 = ga.y*rsqrtf(cq.y*inv_n - m1*m1 + 1e-5f);
  float sh0 = be.x - m0*sc0, sh1 = be.y - m1*sc1;

  float2 v = *reinterpret_cast<const float2*>(&g_act[row*KCL + k2]);
  float vn0 = v.x*sc0 + sh0, vn1 = v.y*sc1 + sh1;
  float mx = fmaxf(vn0, vn1);
  #pragma unroll
  for (int o=16;o>0;o>>=1) mx = fmaxf(mx, __shfl_xor_sync(0xffffffffu, mx, o));
  float e0 = __expf(vn0 - mx), e1 = __expf(vn1 - mx);
  float s = e0 + e1;
  #pragma unroll
  for (int o=16;o>0;o>>=1) s += __shfl_xor_sync(0xffffffffu, s, o);
  float inv = 1.f / s;
  float p0 = e0*inv, p1 = e1*inv;
  *reinterpret_cast<float2*>(&g_act[row*KCL + k2]) = make_float2(p0, p1);
  *reinterpret_cast<float2*>(&sbuf[w][k2]) = make_float2(p0, p1);
  __syncthreads();
  if (tid < KCL){
    float t = 0.f;
    #pragma unroll
    for (int i=0;i<8;i++) t += sbuf[i][tid];
    atomicAdd(&g_asum[b*KCL + tid], t);
  }
}

// ---------------- K4: einsum via bf16 tensor cores + fused transform --------
__global__ __launch_bounds__(256, 2) void einsum_tc_kernel(
    const float* __restrict__ x,
    const float* __restrict__ covw, const float* __restrict__ cw2w){
  __shared__ uint aTh[2][64][12];
  __shared__ uint aTl[2][64][12];
  __shared__ uint xh[2][8][72];
  __shared__ uint xl[2][8][72];
  __shared__ uint qh[2][8][72];
  __shared__ uint ql[2][8][72];
  __shared__ float sAsum[KCL];
  __shared__ float sCol[KCL];
  __shared__ float swp[8];
  int tid = threadIdx.x, warp = tid >> 5, lane = tid & 31;
  int b = blockIdx.y, d0 = blockIdx.x * 64;
  int wm = warp & 1, wn = warp >> 1;
  int px  = tid >> 5;
  int dcx = (tid & 31) * 2;
  int ka  = tid & 63;
  int pa  = (tid >> 6) * 2;
  if (tid < KCL){ sAsum[tid] = g_asum[b*KCL + tid]; sCol[tid] = 0.f; }

  float acc1[2][2][4], acc2[2][2][4];
  #pragma unroll
  for (int mt=0;mt<2;mt++)
    #pragma unroll
    for (int nt=0;nt<2;nt++)
      #pragma unroll
      for (int c=0;c<4;c++){ acc1[mt][nt][c]=0.f; acc2[mt][nt][c]=0.f; }

  const float* xrow = x + (size_t)b*NPTS*DIM + d0;
  const float* arow = g_act + (size_t)b*NPTS*KCL;

  float xv[4], av[4];
  {
    float2 t0 = *reinterpret_cast<const float2*>(&xrow[(2*px  )*DIM + dcx]);
    float2 t1 = *reinterpret_cast<const float2*>(&xrow[(2*px+1)*DIM + dcx]);
    xv[0]=t0.x; xv[1]=t0.y; xv[2]=t1.x; xv[3]=t1.y;
    #pragma unroll
    for (int j=0;j<4;j++) av[j] = arow[(2*pa+j)*KCL + ka];
  }
  {
    float q0=xv[0]*xv[0], q1=xv[1]*xv[1], q2=xv[2]*xv[2], q3=xv[3]*xv[3];
    xh[0][px][dcx  ] = prmt_hi(xv[0], xv[2]);
    xh[0][px][dcx+1] = prmt_hi(xv[1], xv[3]);
    xl[0][px][dcx  ] = cvt_bf2(xv[2]-trunc_bf(xv[2]), xv[0]-trunc_bf(xv[0]));
    xl[0][px][dcx+1] = cvt_bf2(xv[3]-trunc_bf(xv[3]), xv[1]-trunc_bf(xv[1]));
    qh[0][px][dcx  ] = prmt_hi(q0, q2);
    qh[0][px][dcx+1] = prmt_hi(q1, q3);
    ql[0][px][dcx  ] = cvt_bf2(q2-trunc_bf(q2), q0-trunc_bf(q0));
    ql[0][px][dcx+1] = cvt_bf2(q3-trunc_bf(q3), q1-trunc_bf(q1));
    aTh[0][ka][pa  ] = prmt_hi(av[0], av[1]);
    aTh[0][ka][pa+1] = prmt_hi(av[2], av[3]);
    aTl[0][ka][pa  ] = cvt_bf2(av[1]-trunc_bf(av[1]), av[0]-trunc_bf(av[0]));
    aTl[0][ka][pa+1] = cvt_bf2(av[3]-trunc_bf(av[3]), av[2]-trunc_bf(av[2]));
  }
  __syncthreads();

  int r = lane >> 2, cfr = lane & 3;
  for (int t=0; t<32; t++){
    int cur = t & 1;
    bool more = (t+1) < 32;
    if (more){
      int n0 = (t+1)*16;
      float2 t0 = *reinterpret_cast<const float2*>(&xrow[(n0+2*px  )*DIM + dcx]);
      float2 t1 = *reinterpret_cast<const float2*>(&xrow[(n0+2*px+1)*DIM + dcx]);
      xv[0]=t0.x; xv[1]=t0.y; xv[2]=t1.x; xv[3]=t1.y;
      #pragma unroll
      for (int j=0;j<4;j++) av[j] = arow[(n0+2*pa+j)*KCL + ka];
    }
    uint ah[2][4], al[2][4];
    #pragma unroll
    for (int mt=0;mt<2;mt++){
      int rb = wm*32 + mt*16;
      ah[mt][0]=aTh[cur][rb+r  ][cfr];   ah[mt][1]=aTh[cur][rb+r+8][cfr];
      ah[mt][2]=aTh[cur][rb+r  ][cfr+4]; ah[mt][3]=aTh[cur][rb+r+8][cfr+4];
      al[mt][0]=aTl[cur][rb+r  ][cfr];   al[mt][1]=aTl[cur][rb+r+8][cfr];
      al[mt][2]=aTl[cur][rb+r  ][cfr+4]; al[mt][3]=aTl[cur][rb+r+8][cfr+4];
    }
    #pragma unroll
    for (int nt=0;nt<2;nt++){
      int col = wn*16 + nt*8 + r;
      uint bxh0 = xh[cur][cfr][col], bxh1 = xh[cur][cfr+4][col];
      uint bxl0 = xl[cur][cfr][col], bxl1 = xl[cur][cfr+4][col];
      uint bqh0 = qh[cur][cfr][col], bqh1 = qh[cur][cfr+4][col];
      uint bql0 = ql[cur][cfr][col], bql1 = ql[cur][cfr+4][col];
      #pragma unroll
      for (int mt=0;mt<2;mt++){
        mma_bf16(acc1[mt][nt], ah[mt], bxh0, bxh1);
        mma_bf16(acc1[mt][nt], al[mt], bxh0, bxh1);
        mma_bf16(acc1[mt][nt], ah[mt], bxl0, bxl1);
        mma_bf16(acc2[mt][nt], ah[mt], bqh0, bqh1);
        mma_bf16(acc2[mt][nt], al[mt], bqh0, bqh1);
        mma_bf16(acc2[mt][nt], ah[mt], bql0, bql1);
      }
    }
    if (more){
      int nxt = cur ^ 1;
      float q0=xv[0]*xv[0], q1=xv[1]*xv[1], q2=xv[2]*xv[2], q3=xv[3]*xv[3];
      xh[nxt][px][dcx  ] = prmt_hi(xv[0], xv[2]);
      xh[nxt][px][dcx+1] = prmt_hi(xv[1], xv[3]);
      xl[nxt][px][dcx  ] = cvt_bf2(xv[2]-trunc_bf(xv[2]), xv[0]-trunc_bf(xv[0]));
      xl[nxt][px][dcx+1] = cvt_bf2(xv[3]-trunc_bf(xv[3]), xv[1]-trunc_bf(xv[1]));
      qh[nxt][px][dcx  ] = prmt_hi(q0, q2);
      qh[nxt][px][dcx+1] = prmt_hi(q1, q3);
      ql[nxt][px][dcx  ] = cvt_bf2(q2-trunc_bf(q2), q0-trunc_bf(q0));
      ql[nxt][px][dcx+1] = cvt_bf2(q3-trunc_bf(q3), q1-trunc_bf(q1));
      aTh[nxt][ka][pa  ] = prmt_hi(av[0], av[1]);
      aTh[nxt][ka][pa+1] = prmt_hi(av[2], av[3]);
      aTl[nxt][ka][pa  ] = cvt_bf2(av[1]-trunc_bf(av[1]), av[0]-trunc_bf(av[0]));
      aTl[nxt][ka][pa+1] = cvt_bf2(av[3]-trunc_bf(av[3]), av[2]-trunc_bf(av[2]));
    }
    __syncthreads();
  }

  float pn2 = 0.f;
  float pcol[2][2] = {{0.f,0.f},{0.f,0.f}};
  #pragma unroll
  for (int mt=0;mt<2;mt++){
    #pragma unroll
    for (int nt=0;nt<2;nt++){
      #pragma unroll
      for (int c=0;c<4;c++){
        int k   = wm*32 + mt*16 + r + ((c>=2)?8:0);
        int dl  = wn*16 + nt*8 + 2*cfr + (c&1);
        int dgl = d0 + dl;
        int widx = dgl*KCL + k;
        float cwm = cw2w[widx];
        float cvm = covw[widx];
        float asum = sAsum[k];
        float cwv = cvm*cvm + 1e-6f;
        float rc = __fdividef(1.f, cwv);
        float f1r = acc1[mt][nt][c], f2r = acc2[mt][nt][c];
        float f1t = (f1r - asum*cwm) * rc;
        float f2t = (asum*cwm*cwm + f2r - 2.f*f1r*cwm) * rc * rc - asum;
        g_fv1[(b*DIM + dgl)*KCL + k] = f1t;
        g_fv2[(b*DIM + dgl)*KCL + k] = f2t;
        pcol[mt][c>>1 & 1] += f1t*f1t;
        pn2 += f2t*f2t;
      }
    }
  }
  #pragma unroll
  for (int mt=0;mt<2;mt++)
    #pragma unroll
    for (int h=0;h<2;h++){
      int k = wm*32 + mt*16 + r + h*8;
      atomicAdd(&sCol[k], pcol[mt][h]);
    }
  #pragma unroll
  for (int o=16;o>0;o>>=1) pn2 += __shfl_xor_sync(0xffffffffu, pn2, o);
  if (lane==0) swp[warp] = pn2;
  __syncthreads();
  if (tid < KCL) atomicAdd(&g_colnorm[b*KCL + tid], sCol[tid]);
  if (tid == 0){
    float t = 0.f;
    #pragma unroll
    for (int i=0;i<8;i++) t += swp[i];
    atomicAdd(&g_norm2[b], t);
  }
}

// ---------------- K5b: tiny — fold the two-stage norms into scale tables ----
__global__ __launch_bounds__(64) void scale_kernel(){
  int b = blockIdx.x, k = threadIdx.x;
  float cn = g_colnorm[b*KCL + k];
  float inv1 = 1.f / fmaxf(sqrtf(cn), 1e-12f);
  float contrib = cn * inv1 * inv1;
  float t = contrib;
  #pragma unroll
  for (int o=16;o>0;o>>=1) t += __shfl_xor_sync(0xffffffffu, t, o);
  __shared__ float sw[2];
  if ((k&31)==0) sw[k>>5] = t;
  __syncthreads();
  float n1 = sqrtf(sw[0] + sw[1]);
  g_scale1[b*KCL + k] = inv1 / fmaxf(n1, 1e-12f);
  if (k == 0) g_scale2[b] = 1.f / fmaxf(sqrtf(g_norm2[b]), 1e-12f);
}

// ---------------- K6: hidden1 bf16-TC with cp.async 4-stage W pipeline ------
#define FC1_WPAD 260
#define FC1_SMEM (4*16*FC1_WPAD*4 + 2*32*68*4*2)
__global__ __launch_bounds__(256, 2) void gemm_fc1_hmma(
    const float* __restrict__ W){
  extern __shared__ char smemraw[];
  float (*WsS)[16][FC1_WPAD] = reinterpret_cast<float(*)[16][FC1_WPAD]>(smemraw);
  uint (*AhS)[32][68] = reinterpret_cast<uint(*)[32][68]>(smemraw + 4*16*FC1_WPAD*4);
  uint (*AlS)[32][68] = reinterpret_cast<uint(*)[32][68]>(smemraw + 4*16*FC1_WPAD*4 + 2*32*68*4);

  int tid = threadIdx.x;
  int warp = tid >> 5, lane = tid & 31;
  int i0 = blockIdx.y * 2048;
  int o0 = blockIdx.x * 256;

  const float* A;
  int iA0, half1;
  if (i0 < HALF1){ A = g_fv1; iA0 = i0; half1 = 1; }
  else { A = g_fv2; iA0 = i0 - HALF1; half1 = 0; }

  int rA = tid >> 3;
  int pA = (tid & 7) * 8;
  float sreg[16];
  if (half1){
    #pragma unroll
    for (int j=0;j<16;j++) sreg[j] = g_scale1[rA*KCL + ((pA*2 + j) & 63)];
  } else {
    float s = g_scale2[rA];
    #pragma unroll
    for (int j=0;j<16;j++) sreg[j] = s;
  }

  int wrow0 = tid >> 6;
  int wcol0 = (tid & 63) * 4;

  int wcol = warp*32 + (lane >> 2);
  int krow = 2*(lane & 3);
  int r = lane >> 2, cfr = lane & 3;

  float acc[2][4][4];
  #pragma unroll
  for (int mt=0;mt<2;mt++)
    #pragma unroll
    for (int nt=0;nt<4;nt++)
      #pragma unroll
      for (int c=0;c<4;c++) acc[mt][nt][c] = 0.f;

  #pragma unroll
  for (int s=0; s<3; s++){
    const float* base = W + (size_t)(i0 + s*16)*OUTF + o0;
    #pragma unroll
    for (int p=0;p<4;p++){
      int row = wrow0 + p*4;
      uint dst = (uint)__cvta_generic_to_shared(&WsS[s][row][wcol0]);
      const float* src = base + row*OUTF + wcol0;
      asm volatile("cp.async.cg.shared.global [%0], [%1], 16;" :: "r"(dst), "l"(src));
    }
    asm volatile("cp.async.commit_group;");
  }

  {
    const float* ap = &A[rA*HALF1 + iA0 + pA*2];
    float v[16];
    #pragma unroll
    for (int p=0;p<4;p++){
      float4 t4 = *reinterpret_cast<const float4*>(ap + p*4);
      v[p*4+0]=t4.x; v[p*4+1]=t4.y; v[p*4+2]=t4.z; v[p*4+3]=t4.w;
    }
    #pragma unroll
    for (int j=0;j<8;j++){
      float v0 = v[2*j]*sreg[2*j], v1 = v[2*j+1]*sreg[2*j+1];
      AhS[0][rA][pA+j] = prmt_hi(v0, v1);
      AlS[0][rA][pA+j] = cvt_bf2(v1 - trunc_bf(v1), v0 - trunc_bf(v0));
    }
  }
  asm volatile("cp.async.wait_group 2;");
  __syncthreads();

  float vnext[16];
  for (int t=0; t<128; t++){
    int st = t & 3;
    int ss = t >> 3, sin = t & 7, buf = ss & 1;
    if (t+3 < 128){
      const float* base = W + (size_t)(i0 + (t+3)*16)*OUTF + o0;
      int s = (t+3) & 3;
      #pragma unroll
      for (int p=0;p<4;p++){
        int row = wrow0 + p*4;
        uint dst = (uint)__cvta_generic_to_shared(&WsS[s][row][wcol0]);
        const float* src = base + row*OUTF + wcol0;
        asm volatile("cp.async.cg.shared.global [%0], [%1], 16;" :: "r"(dst), "l"(src));
      }
      asm volatile("cp.async.commit_group;");
    }
    if (sin == 0 && ss+1 < 16){
      const float* ap = &A[rA*HALF1 + iA0 + (ss+1)*128 + pA*2];
      #pragma unroll
      for (int p=0;p<4;p++){
        float4 t4 = *reinterpret_cast<const float4*>(ap + p*4);
        vnext[p*4+0]=t4.x; vnext[p*4+1]=t4.y; vnext[p*4+2]=t4.z; vnext[p*4+3]=t4.w;
      }
    }
    float wcur[16];
    #pragma unroll
    for (int nt=0;nt<4;nt++){
      wcur[nt*4+0] = WsS[st][krow  ][wcol + nt*8];
      wcur[nt*4+1] = WsS[st][krow+1][wcol + nt*8];
      wcur[nt*4+2] = WsS[st][krow+8][wcol + nt*8];
      wcur[nt*4+3] = WsS[st][krow+9][wcol + nt*8];
    }
    uint ah[8], al[8];
    #pragma unroll
    for (int mt=0;mt<2;mt++){
      int rr = r + mt*16;
      ah[mt*4+0] = AhS[buf][rr  ][sin*8+cfr];
      ah[mt*4+1] = AhS[buf][rr+8][sin*8+cfr];
      ah[mt*4+2] = AhS[buf][rr  ][sin*8+cfr+4];
      ah[mt*4+3] = AhS[buf][rr+8][sin*8+cfr+4];
      al[mt*4+0] = AlS[buf][rr  ][sin*8+cfr];
      al[mt*4+1] = AlS[buf][rr+8][sin*8+cfr];
      al[mt*4+2] = AlS[buf][rr  ][sin*8+cfr+4];
      al[mt*4+3] = AlS[buf][rr+8][sin*8+cfr+4];
    }
    uint whi[8], wlo[8];
    #pragma unroll
    for (int nt=0;nt<4;nt++){
      float w0 = wcur[nt*4+0], w1 = wcur[nt*4+1];
      float w2 = wcur[nt*4+2], w3 = wcur[nt*4+3];
      whi[nt*2+0] = prmt_hi(w0, w1);
      whi[nt*2+1] = prmt_hi(w2, w3);
      wlo[nt*2+0] = cvt_bf2(w1 - trunc_bf(w1), w0 - trunc_bf(w0));
      wlo[nt*2+1] = cvt_bf2(w3 - trunc_bf(w3), w2 - trunc_bf(w2));
    }
    #pragma unroll
    for (int mt=0;mt<2;mt++){
      #pragma unroll
      for (int nt=0;nt<4;nt++){
        mma_bf16(acc[mt][nt], &ah[mt*4], whi[nt*2], whi[nt*2+1]);
        mma_bf16(acc[mt][nt], &al[mt*4], whi[nt*2], whi[nt*2+1]);
        mma_bf16(acc[mt][nt], &ah[mt*4], wlo[nt*2], wlo[nt*2+1]);
      }
    }
    if (sin == 7 && ss+1 < 16){
      int nb = buf ^ 1;
      #pragma unroll
      for (int j=0;j<8;j++){
        float v0 = vnext[2*j]*sreg[2*j], v1 = vnext[2*j+1]*sreg[2*j+1];
        AhS[nb][rA][pA+j] = prmt_hi(v0, v1);
        AlS[nb][rA][pA+j] = cvt_bf2(v1 - trunc_bf(v1), v0 - trunc_bf(v0));
      }
    }
    if (t+1 < 128){
      if (t+3 < 128){ asm volatile("cp.async.wait_group 2;"); }
      else          { asm volatile("cp.async.wait_group 0;"); }
      __syncthreads();
    }
  }

  #pragma unroll
  for (int mt=0;mt<2;mt++)
    #pragma unroll
    for (int nt=0;nt<4;nt++)
      #pragma unroll
      for (int c=0;c<4;c++){
        int row = (lane>>2) + ((c>=2)?8:0) + mt*16;
        int col = o0 + warp*32 + nt*8 + 2*(lane&3) + (c&1);
        atomicAdd(&g_fvout[row*OUTF + col], acc[mt][nt][c]);
      }
}

// ---------------- K7a: gating GEMM (fp32 FFMA2, small) ----------------------
#define FC_KT 16
__global__ __launch_bounds__(256) void gemm_fc_kernel(
    const float* __restrict__ W, int ichunk){
  __shared__ float Ws[2][FC_KT][256];
  __shared__ float fs[2][FC_KT][32];
  int tid = threadIdx.x;
  int o0 = blockIdx.x * 256;
  int i0 = blockIdx.y * ichunk;
  int og = tid & 63, bg = tid >> 6;
  const float* A = g_fvout; float* out = g_gates;
  int bload = tid & 31;
  int rload0 = (tid >> 5)*2;

  int T = ichunk / FC_KT;
  int roff[4], coff[4];
  #pragma unroll
  for (int p=0;p<4;p++){
    int off = p*1024 + tid*4;
    roff[p] = off >> 8; coff[p] = off & 255;
  }

  ull acc[8][2];
  #pragma unroll
  for (int bb=0;bb<8;bb++){ acc[bb][0]=0ull; acc[bb][1]=0ull; }

  float4 pw[4]; float pa0, pa1;
  {
    #pragma unroll
    for (int p=0;p<4;p++)
      pw[p] = *reinterpret_cast<const float4*>(&W[(i0+roff[p])*OUTF + o0 + coff[p]]);
    pa0 = A[bload*OUTF + i0 + rload0];
    pa1 = A[bload*OUTF + i0 + rload0 + 1];
  }
  #pragma unroll
  for (int p=0;p<4;p++)
    *reinterpret_cast<float4*>(&Ws[0][roff[p]][coff[p]]) = pw[p];
  fs[0][rload0][bload] = pa0;
  fs[0][rload0+1][bload] = pa1;
  __syncthreads();

  for (int t=0; t<T; t++){
    int cur = t & 1;
    bool more = (t+1) < T;
    if (more){
      int i  = i0 + (t+1)*FC_KT;
      #pragma unroll
      for (int p=0;p<4;p++)
        pw[p] = *reinterpret_cast<const float4*>(&W[(i+roff[p])*OUTF + o0 + coff[p]]);
      pa0 = A[bload*OUTF + i + rload0];
      pa1 = A[bload*OUTF + i + rload0 + 1];
    }
    #pragma unroll
    for (int ii=0; ii<FC_KT; ii++){
      const ull* wp = reinterpret_cast<const ull*>(&Ws[cur][ii][og*4]);
      ull w0 = wp[0], w1 = wp[1];
      float4 fa = *reinterpret_cast<const float4*>(&fs[cur][ii][bg*8]);
      float4 fb = *reinterpret_cast<const float4*>(&fs[cur][ii][bg*8+4]);
      ull a0 = pack2(fa.x,fa.x), a1 = pack2(fa.y,fa.y);
      ull a2 = pack2(fa.z,fa.z), a3 = pack2(fa.w,fa.w);
      ull a4 = pack2(fb.x,fb.x), a5 = pack2(fb.y,fb.y);
      ull a6 = pack2(fb.z,fb.z), a7 = pack2(fb.w,fb.w);
      ffma2(acc[0][0], a0, w0); ffma2(acc[0][1], a0, w1);
      ffma2(acc[1][0], a1, w0); ffma2(acc[1][1], a1, w1);
      ffma2(acc[2][0], a2, w0); ffma2(acc[2][1], a2, w1);
      ffma2(acc[3][0], a3, w0); ffma2(acc[3][1], a3, w1);
      ffma2(acc[4][0], a4, w0); ffma2(acc[4][1], a4, w1);
      ffma2(acc[5][0], a5, w0); ffma2(acc[5][1], a5, w1);
      ffma2(acc[6][0], a6, w0); ffma2(acc[6][1], a6, w1);
      ffma2(acc[7][0], a7, w0); ffma2(acc[7][1], a7, w1);
    }
    if (more){
      int nxt = (t+1) & 1;
      #pragma unroll
      for (int p=0;p<4;p++)
        *reinterpret_cast<float4*>(&Ws[nxt][roff[p]][coff[p]]) = pw[p];
      fs[nxt][rload0][bload] = pa0;
      fs[nxt][rload0+1][bload] = pa1;
    }
    __syncthreads();
  }

  #pragma unroll
  for (int bb=0;bb<8;bb++){
    int b = bg*8 + bb;
    #pragma unroll
    for (int t=0;t<2;t++){
      int base = b*OUTF + o0 + og*4 + t*2;
      atomicAdd(&out[base],   lo32(acc[bb][t]));
      atomicAdd(&out[base+1], hi32(acc[bb][t]));
    }
  }
}

// ---------------- K7b: BN2 (batch stats over 32) + sigmoid gate -------------
__global__ __launch_bounds__(256) void bn2_gate_kernel(
    const float* __restrict__ g2, const float* __restrict__ b2,
    float* __restrict__ out){
  int o = blockIdx.x*blockDim.x + threadIdx.x;   // 0..1023
  float m=0.f, s=0.f;
  #pragma unroll 8
  for (int b=0;b<BATCH;b++){ float v = g_gates[b*OUTF + o]; m += v; s += v*v; }
  m *= (1.f/BATCH);
  float var = s*(1.f/BATCH) - m*m;
  float rs = rsqrtf(var + 1e-5f);
  float ga = g2[o], be = b2[o];
  #pragma unroll 8
  for (int b=0;b<BATCH;b++){
    float v = (g_gates[b*OUTF + o] - m)*rs*ga + be;
    float sig = 1.f/(1.f + expf(-v));
    out[b*OUTF + o] = g_fvout[b*OUTF + o] * sig;
  }
}

// ---------------------------------------------------------------------------
extern "C" void kernel_launch(void* const* d_in, const int* in_sizes, int n_in,
                              void* d_out, int out_size){
  const float* x   = (const float*)d_in[0];   // [32,512,1024]
  const float* wc  = (const float*)d_in[1];   // [1024,64]
  const float* cov = (const float*)d_in[2];   // [1024,64]
  const float* cw2 = (const float*)d_in[3];   // [1,1024,64]
  const float* w1  = (const float*)d_in[4];   // [131072,1024]
  const float* g1  = (const float*)d_in[5];   // [64]
  const float* b1  = (const float*)d_in[6];   // [64]
  const float* wg  = (const float*)d_in[7];   // [1024,1024]
  const float* g2  = (const float*)d_in[8];   // [1024]
  const float* b2  = (const float*)d_in[9];   // [1024]
  float* out = (float*)d_out;                 // [32,1024]

  cudaFuncSetAttribute(gemm_fc1_hmma,
      cudaFuncAttributeMaxDynamicSharedMemorySize, FC1_SMEM);

  zero_kernel<<<128, 256>>>();
  gemm_act_kernel<<<256, 256>>>(x, wc);
  bn_softmax_kernel<<<2048, 256>>>(g1, b1);
  einsum_tc_kernel<<<dim3(16, 32), 256>>>(x, cov, cw2);
  scale_kernel<<<BATCH, 64>>>();
  gemm_fc1_hmma<<<dim3(4, 64), 256, FC1_SMEM>>>(w1); // hidden1 (TC + cp.async)
  gemm_fc_kernel<<<dim3(4, 16), 256>>>(wg, 64);      // gating (fp32)
  bn2_gate_kernel<<<4, 256>>>(g2, b2, out);
}

// round 16
// speedup vs baseline: 1.5061x; 1.0199x over previous
#include <cuda_runtime.h>

#define BATCH 32
#define NPTS 512
#define DIM 1024
#define KCL 64
#define NROWS (BATCH*NPTS)      /* 16384 */
#define OUTF 1024
#define IN2 (2*DIM*KCL)         /* 131072 */
#define HALF1 (DIM*KCL)         /* 65536 */

// ---------------- scratch (device globals: no allocations allowed) ----------
__device__ float g_act[NROWS*KCL];          // 4 MB
__device__ float g_colsum[KCL];
__device__ float g_colsumsq[KCL];
__device__ float g_asum[BATCH*KCL];
__device__ float g_fv1[BATCH*DIM*KCL];      // 8 MB
__device__ float g_fv2[BATCH*DIM*KCL];      // 8 MB
__device__ float g_colnorm[BATCH*KCL];
__device__ float g_norm2[BATCH];
__device__ float g_scale1[BATCH*KCL];
__device__ float g_scale2[BATCH];
__device__ float g_fvout[BATCH*OUTF];
__device__ float g_gates[BATCH*OUTF];

typedef unsigned long long ull;
typedef unsigned int uint;

// ---------------- f32x2 helpers (FFMA2: 2 FMAs / instr on sm_103a) ----------
__device__ __forceinline__ ull pack2(float lo, float hi){
  ull r;
  asm("mov.b64 %0, {%1, %2};" : "=l"(r)
      : "r"(__float_as_uint(lo)), "r"(__float_as_uint(hi)));
  return r;
}
__device__ __forceinline__ void ffma2(ull &d, ull a, ull b){
  asm("fma.rn.f32x2 %0, %1, %2, %3;" : "=l"(d) : "l"(a), "l"(b), "l"(d));
}
__device__ __forceinline__ float lo32(ull v){ return __uint_as_float((unsigned)(v & 0xffffffffull)); }
__device__ __forceinline__ float hi32(ull v){ return __uint_as_float((unsigned)(v >> 32)); }

// ---------------- bf16 split helpers ----------------------------------------
__device__ __forceinline__ uint prmt_hi(float a, float b){
  uint r;
  asm("prmt.b32 %0, %1, %2, 0x7632;" : "=r"(r)
      : "r"(__float_as_uint(a)), "r"(__float_as_uint(b)));
  return r;
}
__device__ __forceinline__ float trunc_bf(float v){
  return __uint_as_float(__float_as_uint(v) & 0xffff0000u);
}
__device__ __forceinline__ uint cvt_bf2(float upper, float lower){
  uint r;
  asm("cvt.rn.bf16x2.f32 %0, %1, %2;" : "=r"(r) : "f"(upper), "f"(lower));
  return r;
}
__device__ __forceinline__ void mma_bf16(float* c, const uint* a, uint b0, uint b1){
  asm volatile(
    "mma.sync.aligned.m16n8k16.row.col.f32.bf16.bf16.f32 "
    "{%0,%1,%2,%3},{%4,%5,%6,%7},{%8,%9},{%0,%1,%2,%3};"
    : "+f"(c[0]), "+f"(c[1]), "+f"(c[2]), "+f"(c[3])
    : "r"(a[0]), "r"(a[1]), "r"(a[2]), "r"(a[3]), "r"(b0), "r"(b1));
}

// ---------------- K0: zero the atomic accumulators ---------------------------
__global__ void zero_kernel(){
  int i = blockIdx.x*blockDim.x + threadIdx.x;
  if (i < BATCH*OUTF){ g_fvout[i] = 0.f; g_gates[i] = 0.f; }
  if (i < BATCH*KCL){ g_colnorm[i] = 0.f; g_asum[i] = 0.f; }
  if (i < KCL){ g_colsum[i] = 0.f; g_colsumsq[i] = 0.f; }
  if (i < BATCH) g_norm2[i] = 0.f;
}

// ---------------- K1: act_raw = X @ Wc  (+ column sum / sumsq for BN1) ------
// BK=64: halved barrier count vs BK=32 variant.
__global__ __launch_bounds__(256) void gemm_act_kernel(
    const float* __restrict__ x, const float* __restrict__ wc){
  __shared__ float As[64][65];
  __shared__ float Bs[64][64];
  __shared__ float sSum[KCL], sSq[KCL];
  int tid = threadIdx.x;
  int row0 = blockIdx.x * 64;
  int tx = tid & 15, ty = tid >> 4;
  ull acc[4][2];
  #pragma unroll
  for (int i=0;i<4;i++){ acc[i][0]=0ull; acc[i][1]=0ull; }
  if (tid < KCL){ sSum[tid]=0.f; sSq[tid]=0.f; }

  for (int d0=0; d0<DIM; d0+=64){
    #pragma unroll
    for (int l=tid; l<4096; l+=256){
      int r=l>>6, c=l&63;
      As[r][c] = x[(row0+r)*DIM + d0 + c];
      Bs[r][c] = wc[(d0+r)*KCL + c];
    }
    __syncthreads();
    #pragma unroll
    for (int dd=0; dd<64; dd++){
      const ull* bp = reinterpret_cast<const ull*>(&Bs[dd][tx*4]);
      ull b0 = bp[0], b1 = bp[1];
      #pragma unroll
      for (int i=0;i<4;i++){
        float a = As[ty*4+i][dd];
        ull ap = pack2(a, a);
        ffma2(acc[i][0], ap, b0);
        ffma2(acc[i][1], ap, b1);
      }
    }
    __syncthreads();
  }
  float ps[4]={0,0,0,0}, pq[4]={0,0,0,0};
  #pragma unroll
  for (int i=0;i<4;i++){
    float v0=lo32(acc[i][0]), v1=hi32(acc[i][0]);
    float v2=lo32(acc[i][1]), v3=hi32(acc[i][1]);
    *reinterpret_cast<float4*>(&g_act[(row0+ty*4+i)*KCL + tx*4]) =
        make_float4(v0,v1,v2,v3);
    ps[0]+=v0; ps[1]+=v1; ps[2]+=v2; ps[3]+=v3;
    pq[0]+=v0*v0; pq[1]+=v1*v1; pq[2]+=v2*v2; pq[3]+=v3*v3;
  }
  #pragma unroll
  for (int j=0;j<4;j++){
    atomicAdd(&sSum[tx*4+j], ps[j]);
    atomicAdd(&sSq [tx*4+j], pq[j]);
  }
  __syncthreads();
  if (tid < KCL){
    atomicAdd(&g_colsum[tid],   sSum[tid]);
    atomicAdd(&g_colsumsq[tid], sSq[tid]);
  }
}

// ---------------- K2: BN1 + softmax (warp per row) + fused a_sum ------------
__global__ __launch_bounds__(256) void bn_softmax_kernel(
    const float* __restrict__ gamma, const float* __restrict__ beta){
  __shared__ float sbuf[8][KCL];
  int tid = threadIdx.x;
  int w = tid >> 5, lane = tid & 31;
  int row = blockIdx.x*8 + w;
  int b = row >> 9;
  const float inv_n = 1.f / (float)NROWS;
  int k2 = 2*lane;
  float2 cs = *reinterpret_cast<const float2*>(&g_colsum[k2]);
  float2 cq = *reinterpret_cast<const float2*>(&g_colsumsq[k2]);
  float2 ga = *reinterpret_cast<const float2*>(&gamma[k2]);
  float2 be = *reinterpret_cast<const float2*>(&beta[k2]);
  float m0 = cs.x*inv_n, m1 = cs.y*inv_n;
  float sc0 = ga.x*rsqrtf(cq.x*inv_n - m0*m0 + 1e-5f);
  float sc1 = ga.y*rsqrtf(cq.y*inv_n - m1*m1 + 1e-5f);
  float sh0 = be.x - m0*sc0, sh1 = be.y - m1*sc1;

  float2 v = *reinterpret_cast<const float2*>(&g_act[row*KCL + k2]);
  float vn0 = v.x*sc0 + sh0, vn1 = v.y*sc1 + sh1;
  float mx = fmaxf(vn0, vn1);
  #pragma unroll
  for (int o=16;o>0;o>>=1) mx = fmaxf(mx, __shfl_xor_sync(0xffffffffu, mx, o));
  float e0 = __expf(vn0 - mx), e1 = __expf(vn1 - mx);
  float s = e0 + e1;
  #pragma unroll
  for (int o=16;o>0;o>>=1) s += __shfl_xor_sync(0xffffffffu, s, o);
  float inv = 1.f / s;
  float p0 = e0*inv, p1 = e1*inv;
  *reinterpret_cast<float2*>(&g_act[row*KCL + k2]) = make_float2(p0, p1);
  *reinterpret_cast<float2*>(&sbuf[w][k2]) = make_float2(p0, p1);
  __syncthreads();
  if (tid < KCL){
    float t = 0.f;
    #pragma unroll
    for (int i=0;i<8;i++) t += sbuf[i][tid];
    atomicAdd(&g_asum[b*KCL + tid], t);
  }
}

// ---------------- K4: einsum via bf16 tensor cores + fused transform --------
__global__ __launch_bounds__(256, 2) void einsum_tc_kernel(
    const float* __restrict__ x,
    const float* __restrict__ covw, const float* __restrict__ cw2w){
  __shared__ uint aTh[2][64][12];
  __shared__ uint aTl[2][64][12];
  __shared__ uint xh[2][8][72];
  __shared__ uint xl[2][8][72];
  __shared__ uint qh[2][8][72];
  __shared__ uint ql[2][8][72];
  __shared__ float sAsum[KCL];
  __shared__ float sCol[KCL];
  __shared__ float swp[8];
  int tid = threadIdx.x, warp = tid >> 5, lane = tid & 31;
  int b = blockIdx.y, d0 = blockIdx.x * 64;
  int wm = warp & 1, wn = warp >> 1;
  int px  = tid >> 5;
  int dcx = (tid & 31) * 2;
  int ka  = tid & 63;
  int pa  = (tid >> 6) * 2;
  if (tid < KCL){ sAsum[tid] = g_asum[b*KCL + tid]; sCol[tid] = 0.f; }

  float acc1[2][2][4], acc2[2][2][4];
  #pragma unroll
  for (int mt=0;mt<2;mt++)
    #pragma unroll
    for (int nt=0;nt<2;nt++)
      #pragma unroll
      for (int c=0;c<4;c++){ acc1[mt][nt][c]=0.f; acc2[mt][nt][c]=0.f; }

  const float* xrow = x + (size_t)b*NPTS*DIM + d0;
  const float* arow = g_act + (size_t)b*NPTS*KCL;

  float xv[4], av[4];
  {
    float2 t0 = *reinterpret_cast<const float2*>(&xrow[(2*px  )*DIM + dcx]);
    float2 t1 = *reinterpret_cast<const float2*>(&xrow[(2*px+1)*DIM + dcx]);
    xv[0]=t0.x; xv[1]=t0.y; xv[2]=t1.x; xv[3]=t1.y;
    #pragma unroll
    for (int j=0;j<4;j++) av[j] = arow[(2*pa+j)*KCL + ka];
  }
  {
    float q0=xv[0]*xv[0], q1=xv[1]*xv[1], q2=xv[2]*xv[2], q3=xv[3]*xv[3];
    xh[0][px][dcx  ] = prmt_hi(xv[0], xv[2]);
    xh[0][px][dcx+1] = prmt_hi(xv[1], xv[3]);
    xl[0][px][dcx  ] = cvt_bf2(xv[2]-trunc_bf(xv[2]), xv[0]-trunc_bf(xv[0]));
    xl[0][px][dcx+1] = cvt_bf2(xv[3]-trunc_bf(xv[3]), xv[1]-trunc_bf(xv[1]));
    qh[0][px][dcx  ] = prmt_hi(q0, q2);
    qh[0][px][dcx+1] = prmt_hi(q1, q3);
    ql[0][px][dcx  ] = cvt_bf2(q2-trunc_bf(q2), q0-trunc_bf(q0));
    ql[0][px][dcx+1] = cvt_bf2(q3-trunc_bf(q3), q1-trunc_bf(q1));
    aTh[0][ka][pa  ] = prmt_hi(av[0], av[1]);
    aTh[0][ka][pa+1] = prmt_hi(av[2], av[3]);
    aTl[0][ka][pa  ] = cvt_bf2(av[1]-trunc_bf(av[1]), av[0]-trunc_bf(av[0]));
    aTl[0][ka][pa+1] = cvt_bf2(av[3]-trunc_bf(av[3]), av[2]-trunc_bf(av[2]));
  }
  __syncthreads();

  int r = lane >> 2, cfr = lane & 3;
  for (int t=0; t<32; t++){
    int cur = t & 1;
    bool more = (t+1) < 32;
    if (more){
      int n0 = (t+1)*16;
      float2 t0 = *reinterpret_cast<const float2*>(&xrow[(n0+2*px  )*DIM + dcx]);
      float2 t1 = *reinterpret_cast<const float2*>(&xrow[(n0+2*px+1)*DIM + dcx]);
      xv[0]=t0.x; xv[1]=t0.y; xv[2]=t1.x; xv[3]=t1.y;
      #pragma unroll
      for (int j=0;j<4;j++) av[j] = arow[(n0+2*pa+j)*KCL + ka];
    }
    uint ah[2][4], al[2][4];
    #pragma unroll
    for (int mt=0;mt<2;mt++){
      int rb = wm*32 + mt*16;
      ah[mt][0]=aTh[cur][rb+r  ][cfr];   ah[mt][1]=aTh[cur][rb+r+8][cfr];
      ah[mt][2]=aTh[cur][rb+r  ][cfr+4]; ah[mt][3]=aTh[cur][rb+r+8][cfr+4];
      al[mt][0]=aTl[cur][rb+r  ][cfr];   al[mt][1]=aTl[cur][rb+r+8][cfr];
      al[mt][2]=aTl[cur][rb+r  ][cfr+4]; al[mt][3]=aTl[cur][rb+r+8][cfr+4];
    }
    #pragma unroll
    for (int nt=0;nt<2;nt++){
      int col = wn*16 + nt*8 + r;
      uint bxh0 = xh[cur][cfr][col], bxh1 = xh[cur][cfr+4][col];
      uint bxl0 = xl[cur][cfr][col], bxl1 = xl[cur][cfr+4][col];
      uint bqh0 = qh[cur][cfr][col], bqh1 = qh[cur][cfr+4][col];
      uint bql0 = ql[cur][cfr][col], bql1 = ql[cur][cfr+4][col];
      #pragma unroll
      for (int mt=0;mt<2;mt++){
        mma_bf16(acc1[mt][nt], ah[mt], bxh0, bxh1);
        mma_bf16(acc1[mt][nt], al[mt], bxh0, bxh1);
        mma_bf16(acc1[mt][nt], ah[mt], bxl0, bxl1);
        mma_bf16(acc2[mt][nt], ah[mt], bqh0, bqh1);
        mma_bf16(acc2[mt][nt], al[mt], bqh0, bqh1);
        mma_bf16(acc2[mt][nt], ah[mt], bql0, bql1);
      }
    }
    if (more){
      int nxt = cur ^ 1;
      float q0=xv[0]*xv[0], q1=xv[1]*xv[1], q2=xv[2]*xv[2], q3=xv[3]*xv[3];
      xh[nxt][px][dcx  ] = prmt_hi(xv[0], xv[2]);
      xh[nxt][px][dcx+1] = prmt_hi(xv[1], xv[3]);
      xl[nxt][px][dcx  ] = cvt_bf2(xv[2]-trunc_bf(xv[2]), xv[0]-trunc_bf(xv[0]));
      xl[nxt][px][dcx+1] = cvt_bf2(xv[3]-trunc_bf(xv[3]), xv[1]-trunc_bf(xv[1]));
      qh[nxt][px][dcx  ] = prmt_hi(q0, q2);
      qh[nxt][px][dcx+1] = prmt_hi(q1, q3);
      ql[nxt][px][dcx  ] = cvt_bf2(q2-trunc_bf(q2), q0-trunc_bf(q0));
      ql[nxt][px][dcx+1] = cvt_bf2(q3-trunc_bf(q3), q1-trunc_bf(q1));
      aTh[nxt][ka][pa  ] = prmt_hi(av[0], av[1]);
      aTh[nxt][ka][pa+1] = prmt_hi(av[2], av[3]);
      aTl[nxt][ka][pa  ] = cvt_bf2(av[1]-trunc_bf(av[1]), av[0]-trunc_bf(av[0]));
      aTl[nxt][ka][pa+1] = cvt_bf2(av[3]-trunc_bf(av[3]), av[2]-trunc_bf(av[2]));
    }
    __syncthreads();
  }

  float pn2 = 0.f;
  float pcol[2][2] = {{0.f,0.f},{0.f,0.f}};
  #pragma unroll
  for (int mt=0;mt<2;mt++){
    #pragma unroll
    for (int nt=0;nt<2;nt++){
      #pragma unroll
      for (int c=0;c<4;c++){
        int k   = wm*32 + mt*16 + r + ((c>=2)?8:0);
        int dl  = wn*16 + nt*8 + 2*cfr + (c&1);
        int dgl = d0 + dl;
        int widx = dgl*KCL + k;
        float cwm = cw2w[widx];
        float cvm = covw[widx];
        float asum = sAsum[k];
        float cwv = cvm*cvm + 1e-6f;
        float rc = __fdividef(1.f, cwv);
        float f1r = acc1[mt][nt][c], f2r = acc2[mt][nt][c];
        float f1t = (f1r - asum*cwm) * rc;
        float f2t = (asum*cwm*cwm + f2r - 2.f*f1r*cwm) * rc * rc - asum;
        g_fv1[(b*DIM + dgl)*KCL + k] = f1t;
        g_fv2[(b*DIM + dgl)*KCL + k] = f2t;
        pcol[mt][c>>1 & 1] += f1t*f1t;
        pn2 += f2t*f2t;
      }
    }
  }
  #pragma unroll
  for (int mt=0;mt<2;mt++)
    #pragma unroll
    for (int h=0;h<2;h++){
      int k = wm*32 + mt*16 + r + h*8;
      atomicAdd(&sCol[k], pcol[mt][h]);
    }
  #pragma unroll
  for (int o=16;o>0;o>>=1) pn2 += __shfl_xor_sync(0xffffffffu, pn2, o);
  if (lane==0) swp[warp] = pn2;
  __syncthreads();
  if (tid < KCL) atomicAdd(&g_colnorm[b*KCL + tid], sCol[tid]);
  if (tid == 0){
    float t = 0.f;
    #pragma unroll
    for (int i=0;i<8;i++) t += swp[i];
    atomicAdd(&g_norm2[b], t);
  }
}

// ---------------- K5b: tiny — fold the two-stage norms into scale tables ----
__global__ __launch_bounds__(64) void scale_kernel(){
  int b = blockIdx.x, k = threadIdx.x;
  float cn = g_colnorm[b*KCL + k];
  float inv1 = 1.f / fmaxf(sqrtf(cn), 1e-12f);
  float contrib = cn * inv1 * inv1;
  float t = contrib;
  #pragma unroll
  for (int o=16;o>0;o>>=1) t += __shfl_xor_sync(0xffffffffu, t, o);
  __shared__ float sw[2];
  if ((k&31)==0) sw[k>>5] = t;
  __syncthreads();
  float n1 = sqrtf(sw[0] + sw[1]);
  g_scale1[b*KCL + k] = inv1 / fmaxf(n1, 1e-12f);
  if (k == 0) g_scale2[b] = 1.f / fmaxf(sqrtf(g_norm2[b]), 1e-12f);
}

// ---------------- K6: hidden1 bf16-TC with cp.async 4-stage W pipeline ------
// ichunk=1024 (64 steps, 8 supersteps): finer-grained blocks for load balance.
#define FC1_WPAD 260
#define FC1_SMEM (4*16*FC1_WPAD*4 + 2*32*68*4*2)
#define FC1_STEPS 64
#define FC1_SS 8
__global__ __launch_bounds__(256, 2) void gemm_fc1_hmma(
    const float* __restrict__ W){
  extern __shared__ char smemraw[];
  float (*WsS)[16][FC1_WPAD] = reinterpret_cast<float(*)[16][FC1_WPAD]>(smemraw);
  uint (*AhS)[32][68] = reinterpret_cast<uint(*)[32][68]>(smemraw + 4*16*FC1_WPAD*4);
  uint (*AlS)[32][68] = reinterpret_cast<uint(*)[32][68]>(smemraw + 4*16*FC1_WPAD*4 + 2*32*68*4);

  int tid = threadIdx.x;
  int warp = tid >> 5, lane = tid & 31;
  int i0 = blockIdx.y * 1024;
  int o0 = blockIdx.x * 256;

  const float* A;
  int iA0, half1;
  if (i0 < HALF1){ A = g_fv1; iA0 = i0; half1 = 1; }
  else { A = g_fv2; iA0 = i0 - HALF1; half1 = 0; }

  int rA = tid >> 3;
  int pA = (tid & 7) * 8;
  float sreg[16];
  if (half1){
    #pragma unroll
    for (int j=0;j<16;j++) sreg[j] = g_scale1[rA*KCL + ((pA*2 + j) & 63)];
  } else {
    float s = g_scale2[rA];
    #pragma unroll
    for (int j=0;j<16;j++) sreg[j] = s;
  }

  int wrow0 = tid >> 6;
  int wcol0 = (tid & 63) * 4;

  int wcol = warp*32 + (lane >> 2);
  int krow = 2*(lane & 3);
  int r = lane >> 2, cfr = lane & 3;

  float acc[2][4][4];
  #pragma unroll
  for (int mt=0;mt<2;mt++)
    #pragma unroll
    for (int nt=0;nt<4;nt++)
      #pragma unroll
      for (int c=0;c<4;c++) acc[mt][nt][c] = 0.f;

  #pragma unroll
  for (int s=0; s<3; s++){
    const float* base = W + (size_t)(i0 + s*16)*OUTF + o0;
    #pragma unroll
    for (int p=0;p<4;p++){
      int row = wrow0 + p*4;
      uint dst = (uint)__cvta_generic_to_shared(&WsS[s][row][wcol0]);
      const float* src = base + row*OUTF + wcol0;
      asm volatile("cp.async.cg.shared.global [%0], [%1], 16;" :: "r"(dst), "l"(src));
    }
    asm volatile("cp.async.commit_group;");
  }

  {
    const float* ap = &A[rA*HALF1 + iA0 + pA*2];
    float v[16];
    #pragma unroll
    for (int p=0;p<4;p++){
      float4 t4 = *reinterpret_cast<const float4*>(ap + p*4);
      v[p*4+0]=t4.x; v[p*4+1]=t4.y; v[p*4+2]=t4.z; v[p*4+3]=t4.w;
    }
    #pragma unroll
    for (int j=0;j<8;j++){
      float v0 = v[2*j]*sreg[2*j], v1 = v[2*j+1]*sreg[2*j+1];
      AhS[0][rA][pA+j] = prmt_hi(v0, v1);
      AlS[0][rA][pA+j] = cvt_bf2(v1 - trunc_bf(v1), v0 - trunc_bf(v0));
    }
  }
  asm volatile("cp.async.wait_group 2;");
  __syncthreads();

  float vnext[16];
  for (int t=0; t<FC1_STEPS; t++){
    int st = t & 3;
    int ss = t >> 3, sin = t & 7, buf = ss & 1;
    if (t+3 < FC1_STEPS){
      const float* base = W + (size_t)(i0 + (t+3)*16)*OUTF + o0;
      int s = (t+3) & 3;
      #pragma unroll
      for (int p=0;p<4;p++){
        int row = wrow0 + p*4;
        uint dst = (uint)__cvta_generic_to_shared(&WsS[s][row][wcol0]);
        const float* src = base + row*OUTF + wcol0;
        asm volatile("cp.async.cg.shared.global [%0], [%1], 16;" :: "r"(dst), "l"(src));
      }
      asm volatile("cp.async.commit_group;");
    }
    if (sin == 0 && ss+1 < FC1_SS){
      const float* ap = &A[rA*HALF1 + iA0 + (ss+1)*128 + pA*2];
      #pragma unroll
      for (int p=0;p<4;p++){
        float4 t4 = *reinterpret_cast<const float4*>(ap + p*4);
        vnext[p*4+0]=t4.x; vnext[p*4+1]=t4.y; vnext[p*4+2]=t4.z; vnext[p*4+3]=t4.w;
      }
    }
    float wcur[16];
    #pragma unroll
    for (int nt=0;nt<4;nt++){
      wcur[nt*4+0] = WsS[st][krow  ][wcol + nt*8];
      wcur[nt*4+1] = WsS[st][krow+1][wcol + nt*8];
      wcur[nt*4+2] = WsS[st][krow+8][wcol + nt*8];
      wcur[nt*4+3] = WsS[st][krow+9][wcol + nt*8];
    }
    uint ah[8], al[8];
    #pragma unroll
    for (int mt=0;mt<2;mt++){
      int rr = r + mt*16;
      ah[mt*4+0] = AhS[buf][rr  ][sin*8+cfr];
      ah[mt*4+1] = AhS[buf][rr+8][sin*8+cfr];
      ah[mt*4+2] = AhS[buf][rr  ][sin*8+cfr+4];
      ah[mt*4+3] = AhS[buf][rr+8][sin*8+cfr+4];
      al[mt*4+0] = AlS[buf][rr  ][sin*8+cfr];
      al[mt*4+1] = AlS[buf][rr+8][sin*8+cfr];
      al[mt*4+2] = AlS[buf][rr  ][sin*8+cfr+4];
      al[mt*4+3] = AlS[buf][rr+8][sin*8+cfr+4];
    }
    uint whi[8], wlo[8];
    #pragma unroll
    for (int nt=0;nt<4;nt++){
      float w0 = wcur[nt*4+0], w1 = wcur[nt*4+1];
      float w2 = wcur[nt*4+2], w3 = wcur[nt*4+3];
      whi[nt*2+0] = prmt_hi(w0, w1);
      whi[nt*2+1] = prmt_hi(w2, w3);
      wlo[nt*2+0] = cvt_bf2(w1 - trunc_bf(w1), w0 - trunc_bf(w0));
      wlo[nt*2+1] = cvt_bf2(w3 - trunc_bf(w3), w2 - trunc_bf(w2));
    }
    #pragma unroll
    for (int mt=0;mt<2;mt++){
      #pragma unroll
      for (int nt=0;nt<4;nt++){
        mma_bf16(acc[mt][nt], &ah[mt*4], whi[nt*2], whi[nt*2+1]);
        mma_bf16(acc[mt][nt], &al[mt*4], whi[nt*2], whi[nt*2+1]);
        mma_bf16(acc[mt][nt], &ah[mt*4], wlo[nt*2], wlo[nt*2+1]);
      }
    }
    if (sin == 7 && ss+1 < FC1_SS){
      int nb = buf ^ 1;
      #pragma unroll
      for (int j=0;j<8;j++){
        float v0 = vnext[2*j]*sreg[2*j], v1 = vnext[2*j+1]*sreg[2*j+1];
        AhS[nb][rA][pA+j] = prmt_hi(v0, v1);
        AlS[nb][rA][pA+j] = cvt_bf2(v1 - trunc_bf(v1), v0 - trunc_bf(v0));
      }
    }
    if (t+1 < FC1_STEPS){
      if (t+3 < FC1_STEPS){ asm volatile("cp.async.wait_group 2;"); }
      else                { asm volatile("cp.async.wait_group 0;"); }
      __syncthreads();
    }
  }

  #pragma unroll
  for (int mt=0;mt<2;mt++)
    #pragma unroll
    for (int nt=0;nt<4;nt++)
      #pragma unroll
      for (int c=0;c<4;c++){
        int row = (lane>>2) + ((c>=2)?8:0) + mt*16;
        int col = o0 + warp*32 + nt*8 + 2*(lane&3) + (c&1);
        atomicAdd(&g_fvout[row*OUTF + col], acc[mt][nt][c]);
      }
}

// ---------------- K7a: gating GEMM (fp32 FFMA2, small) ----------------------
#define FC_KT 16
__global__ __launch_bounds__(256) void gemm_fc_kernel(
    const float* __restrict__ W, int ichunk){
  __shared__ float Ws[2][FC_KT][256];
  __shared__ float fs[2][FC_KT][32];
  int tid = threadIdx.x;
  int o0 = blockIdx.x * 256;
  int i0 = blockIdx.y * ichunk;
  int og = tid & 63, bg = tid >> 6;
  const float* A = g_fvout; float* out = g_gates;
  int bload = tid & 31;
  int rload0 = (tid >> 5)*2;

  int T = ichunk / FC_KT;
  int roff[4], coff[4];
  #pragma unroll
  for (int p=0;p<4;p++){
    int off = p*1024 + tid*4;
    roff[p] = off >> 8; coff[p] = off & 255;
  }

  ull acc[8][2];
  #pragma unroll
  for (int bb=0;bb<8;bb++){ acc[bb][0]=0ull; acc[bb][1]=0ull; }

  float4 pw[4]; float pa0, pa1;
  {
    #pragma unroll
    for (int p=0;p<4;p++)
      pw[p] = *reinterpret_cast<const float4*>(&W[(i0+roff[p])*OUTF + o0 + coff[p]]);
    pa0 = A[bload*OUTF + i0 + rload0];
    pa1 = A[bload*OUTF + i0 + rload0 + 1];
  }
  #pragma unroll
  for (int p=0;p<4;p++)
    *reinterpret_cast<float4*>(&Ws[0][roff[p]][coff[p]]) = pw[p];
  fs[0][rload0][bload] = pa0;
  fs[0][rload0+1][bload] = pa1;
  __syncthreads();

  for (int t=0; t<T; t++){
    int cur = t & 1;
    bool more = (t+1) < T;
    if (more){
      int i  = i0 + (t+1)*FC_KT;
      #pragma unroll
      for (int p=0;p<4;p++)
        pw[p] = *reinterpret_cast<const float4*>(&W[(i+roff[p])*OUTF + o0 + coff[p]]);
      pa0 = A[bload*OUTF + i + rload0];
      pa1 = A[bload*OUTF + i + rload0 + 1];
    }
    #pragma unroll
    for (int ii=0; ii<FC_KT; ii++){
      const ull* wp = reinterpret_cast<const ull*>(&Ws[cur][ii][og*4]);
      ull w0 = wp[0], w1 = wp[1];
      float4 fa = *reinterpret_cast<const float4*>(&fs[cur][ii][bg*8]);
      float4 fb = *reinterpret_cast<const float4*>(&fs[cur][ii][bg*8+4]);
      ull a0 = pack2(fa.x,fa.x), a1 = pack2(fa.y,fa.y);
      ull a2 = pack2(fa.z,fa.z), a3 = pack2(fa.w,fa.w);
      ull a4 = pack2(fb.x,fb.x), a5 = pack2(fb.y,fb.y);
      ull a6 = pack2(fb.z,fb.z), a7 = pack2(fb.w,fb.w);
      ffma2(acc[0][0], a0, w0); ffma2(acc[0][1], a0, w1);
      ffma2(acc[1][0], a1, w0); ffma2(acc[1][1], a1, w1);
      ffma2(acc[2][0], a2, w0); ffma2(acc[2][1], a2, w1);
      ffma2(acc[3][0], a3, w0); ffma2(acc[3][1], a3, w1);
      ffma2(acc[4][0], a4, w0); ffma2(acc[4][1], a4, w1);
      ffma2(acc[5][0], a5, w0); ffma2(acc[5][1], a5, w1);
      ffma2(acc[6][0], a6, w0); ffma2(acc[6][1], a6, w1);
      ffma2(acc[7][0], a7, w0); ffma2(acc[7][1], a7, w1);
    }
    if (more){
      int nxt = (t+1) & 1;
      #pragma unroll
      for (int p=0;p<4;p++)
        *reinterpret_cast<float4*>(&Ws[nxt][roff[p]][coff[p]]) = pw[p];
      fs[nxt][rload0][bload] = pa0;
      fs[nxt][rload0+1][bload] = pa1;
    }
    __syncthreads();
  }

  #pragma unroll
  for (int bb=0;bb<8;bb++){
    int b = bg*8 + bb;
    #pragma unroll
    for (int t=0;t<2;t++){
      int base = b*OUTF + o0 + og*4 + t*2;
      atomicAdd(&out[base],   lo32(acc[bb][t]));
      atomicAdd(&out[base+1], hi32(acc[bb][t]));
    }
  }
}

// ---------------- K7b: BN2 (batch stats over 32) + sigmoid gate -------------
__global__ __launch_bounds__(256) void bn2_gate_kernel(
    const float* __restrict__ g2, const float* __restrict__ b2,
    float* __restrict__ out){
  int o = blockIdx.x*blockDim.x + threadIdx.x;   // 0..1023
  float m=0.f, s=0.f;
  #pragma unroll 8
  for (int b=0;b<BATCH;b++){ float v = g_gates[b*OUTF + o]; m += v; s += v*v; }
  m *= (1.f/BATCH);
  float var = s*(1.f/BATCH) - m*m;
  float rs = rsqrtf(var + 1e-5f);
  float ga = g2[o], be = b2[o];
  #pragma unroll 8
  for (int b=0;b<BATCH;b++){
    float v = (g_gates[b*OUTF + o] - m)*rs*ga + be;
    float sig = 1.f/(1.f + expf(-v));
    out[b*OUTF + o] = g_fvout[b*OUTF + o] * sig;
  }
}

// ---------------------------------------------------------------------------
extern "C" void kernel_launch(void* const* d_in, const int* in_sizes, int n_in,
                              void* d_out, int out_size){
  const float* x   = (const float*)d_in[0];   // [32,512,1024]
  const float* wc  = (const float*)d_in[1];   // [1024,64]
  const float* cov = (const float*)d_in[2];   // [1024,64]
  const float* cw2 = (const float*)d_in[3];   // [1,1024,64]
  const float* w1  = (const float*)d_in[4];   // [131072,1024]
  const float* g1  = (const float*)d_in[5];   // [64]
  const float* b1  = (const float*)d_in[6];   // [64]
  const float* wg  = (const float*)d_in[7];   // [1024,1024]
  const float* g2  = (const float*)d_in[8];   // [1024]
  const float* b2  = (const float*)d_in[9];   // [1024]
  float* out = (float*)d_out;                 // [32,1024]

  cudaFuncSetAttribute(gemm_fc1_hmma,
      cudaFuncAttributeMaxDynamicSharedMemorySize, FC1_SMEM);

  zero_kernel<<<128, 256>>>();
  gemm_act_kernel<<<256, 256>>>(x, wc);
  bn_softmax_kernel<<<2048, 256>>>(g1, b1);
  einsum_tc_kernel<<<dim3(16, 32), 256>>>(x, cov, cw2);
  scale_kernel<<<BATCH, 64>>>();
  gemm_fc1_hmma<<<dim3(4, 128), 256, FC1_SMEM>>>(w1); // hidden1 (TC + cp.async)
  gemm_fc_kernel<<<dim3(4, 16), 256>>>(wg, 64);       // gating (fp32)
  bn2_gate_kernel<<<4, 256>>>(g2, b2, out);
}